// round 5
// baseline (speedup 1.0000x reference)
#include <cuda_runtime.h>
#include <cuda_bf16.h>
#include <cstdint>

// ---------------------------------------------------------------------------
// Problem constants
// ---------------------------------------------------------------------------
#define BN   8
#define SEQ  2048
#define DIN  1024
#define DM   1024
#define NTOK (BN*SEQ)          // 16384

// ---------------------------------------------------------------------------
// Scratch (__device__ globals; allocation-free rule)
// ---------------------------------------------------------------------------
__device__ __nv_bfloat16 g_Xq_h[(size_t)NTOK*DIN];
__device__ __nv_bfloat16 g_Xq_l[(size_t)NTOK*DIN];
__device__ __nv_bfloat16 g_Xk_h[(size_t)NTOK*DIN];
__device__ __nv_bfloat16 g_Xk_l[(size_t)NTOK*DIN];
__device__ __nv_bfloat16 g_Xv_h[(size_t)NTOK*DIN];
__device__ __nv_bfloat16 g_Xv_l[(size_t)NTOK*DIN];
__device__ __nv_bfloat16 g_Wq_h[(size_t)DM*DIN];
__device__ __nv_bfloat16 g_Wq_l[(size_t)DM*DIN];
__device__ __nv_bfloat16 g_Wk_h[(size_t)DM*DIN];
__device__ __nv_bfloat16 g_Wk_l[(size_t)DM*DIN];
__device__ __nv_bfloat16 g_Wv_h[(size_t)DM*DIN];
__device__ __nv_bfloat16 g_Wv_l[(size_t)DM*DIN];
__device__ __nv_bfloat16 g_Q_h [(size_t)NTOK*DM];
__device__ __nv_bfloat16 g_Q_l [(size_t)NTOK*DM];
__device__ __nv_bfloat16 g_K_h [(size_t)NTOK*DM];
__device__ __nv_bfloat16 g_K_l [(size_t)NTOK*DM];
__device__ __nv_bfloat16 g_Vt_h[(size_t)BN*DM*SEQ];     // [b][v][s]
__device__ __nv_bfloat16 g_Vt_l[(size_t)BN*DM*SEQ];
__device__ float         g_S  [(size_t)BN*SEQ*SEQ];
__device__ __nv_bfloat16 g_P_h[(size_t)BN*SEQ*SEQ];
__device__ __nv_bfloat16 g_P_l[(size_t)BN*SEQ*SEQ];

// ---------------------------------------------------------------------------
// Helpers available on base compute_103
// ---------------------------------------------------------------------------
__device__ __forceinline__ uint32_t smem_u32(const void* p) {
    uint32_t a;
    asm("{ .reg .u64 t; cvta.to.shared.u64 t, %1; cvt.u32.u64 %0, t; }"
        : "=r"(a) : "l"(p));
    return a;
}
__device__ __forceinline__ void cp16(uint32_t dst, const void* src) {
    asm volatile("cp.async.cg.shared.global [%0], [%1], 16;" :: "r"(dst), "l"(src));
}
#define CP_COMMIT()  asm volatile("cp.async.commit_group;" ::: "memory")
#define CP_WAIT(N)   asm volatile("cp.async.wait_group %0;" :: "n"(N) : "memory")

__device__ __forceinline__ void mma16816(float* c, const uint32_t* a,
                                         uint32_t b0, uint32_t b1) {
    asm volatile(
        "mma.sync.aligned.m16n8k16.row.col.f32.bf16.bf16.f32 "
        "{%0,%1,%2,%3}, {%4,%5,%6,%7}, {%8,%9}, {%0,%1,%2,%3};"
        : "+f"(c[0]), "+f"(c[1]), "+f"(c[2]), "+f"(c[3])
        : "r"(a[0]), "r"(a[1]), "r"(a[2]), "r"(a[3]), "r"(b0), "r"(b1));
}

__device__ __forceinline__ void split2(float v, __nv_bfloat16& h, __nv_bfloat16& l) {
    h = __float2bfloat16(v);
    l = __float2bfloat16(v - __bfloat162float(h));
}

// ---------------------------------------------------------------------------
// tcgen05 helpers — ONLY compiled when the build has a compute_103a pass.
// ---------------------------------------------------------------------------
#if defined(__CUDA_ARCH_FEAT_SM103_ALL)
__device__ __forceinline__ uint32_t elect_one_pred() {
    uint32_t pred;
    asm volatile(
        "{\n\t.reg .pred p;\n\t"
        "elect.sync _|p, 0xFFFFFFFF;\n\t"
        "selp.b32 %0, 1, 0, p;\n\t}"
        : "=r"(pred));
    return pred;
}
#define MBARRIER_INIT(addr, cnt) \
    asm volatile("mbarrier.init.shared.b64 [%0], %1;" :: "r"((uint32_t)(addr)), "r"((uint32_t)(cnt)) : "memory")
#define MBARRIER_WAIT_PARITY(mbar, par) do { \
    uint32_t _m = (uint32_t)(mbar), _p = (uint32_t)(par), _d; \
    asm volatile("{\n\t.reg .pred p;\n\t" \
        "mbarrier.try_wait.parity.acquire.cta.shared::cta.b64 p, [%1], %2;\n\t" \
        "selp.b32 %0, 1, 0, p;\n\t}" : "=r"(_d) : "r"(_m), "r"(_p) : "memory"); \
    if (!_d) { \
        asm volatile("{\n\t.reg .pred P1;\n\t" \
            "WL_%=:\n\t" \
            "mbarrier.try_wait.parity.acquire.cta.shared::cta.b64 P1, [%0], %1, 0x989680;\n\t" \
            "@P1 bra.uni WD_%=;\n\tbra.uni WL_%=;\n\tWD_%=:\n\t}" \
            :: "r"(_m), "r"(_p) : "memory"); \
    } \
} while (0)
#define TCGEN05_ALLOC(a, n) \
    asm volatile("tcgen05.alloc.cta_group::1.sync.aligned.shared::cta.b32 [%0], %1;" \
        :: "r"((uint32_t)(a)), "r"((uint32_t)(n)) : "memory")
#define TCGEN05_RELINQUISH() \
    asm volatile("tcgen05.relinquish_alloc_permit.cta_group::1.sync.aligned;")
#define TCGEN05_DEALLOC(t, n) \
    asm volatile("tcgen05.dealloc.cta_group::1.sync.aligned.b32 %0, %1;" :: "r"(t), "r"((uint32_t)(n)))
#define TCGEN05_COMMIT(m) \
    asm volatile("tcgen05.commit.cta_group::1.mbarrier::arrive::one.shared::cluster.b64 [%0];" \
        :: "r"((uint32_t)(m)) : "memory")
#define TCGEN05_WAIT_LD()    asm volatile("tcgen05.wait::ld.sync.aligned;" ::: "memory")
#define TCGEN05_FENCE_AFTER() asm volatile("tcgen05.fence::after_thread_sync;" ::: "memory")
#define FENCE_PROXY_ASYNC()  asm volatile("fence.proxy.async.shared::cta;" ::: "memory")
#define TCGEN05_LD_32X32B_X32(r, ta) \
    asm volatile( \
        "tcgen05.ld.sync.aligned.32x32b.x32.b32 " \
        "{%0, %1, %2, %3, %4, %5, %6, %7, " \
        " %8, %9, %10, %11, %12, %13, %14, %15, " \
        " %16, %17, %18, %19, %20, %21, %22, %23, " \
        " %24, %25, %26, %27, %28, %29, %30, %31}, [%32];" \
        : "=r"((r)[0]),  "=r"((r)[1]),  "=r"((r)[2]),  "=r"((r)[3]), \
          "=r"((r)[4]),  "=r"((r)[5]),  "=r"((r)[6]),  "=r"((r)[7]), \
          "=r"((r)[8]),  "=r"((r)[9]),  "=r"((r)[10]), "=r"((r)[11]), \
          "=r"((r)[12]), "=r"((r)[13]), "=r"((r)[14]), "=r"((r)[15]), \
          "=r"((r)[16]), "=r"((r)[17]), "=r"((r)[18]), "=r"((r)[19]), \
          "=r"((r)[20]), "=r"((r)[21]), "=r"((r)[22]), "=r"((r)[23]), \
          "=r"((r)[24]), "=r"((r)[25]), "=r"((r)[26]), "=r"((r)[27]), \
          "=r"((r)[28]), "=r"((r)[29]), "=r"((r)[30]), "=r"((r)[31]) \
        : "r"(ta))
static constexpr uint64_t SMEM_DESC_BASE_SW128 =
    (uint64_t(2)  << 61) | (uint64_t(1) << 46) | (uint64_t(64) << 32) | (uint64_t(1) << 16);
#define MAKE_SMEM_DESC(ba) (SMEM_DESC_BASE_SW128 | ((uint64_t)((ba) >> 4) & 0x3FFF))
#define SWZ128(off) ((off) ^ (((off) >> 3) & 0x70))
__device__ __forceinline__ void mma_bf16_ss(uint32_t d, uint64_t ad, uint64_t bd,
                                            uint32_t idesc, bool acc) {
    uint32_t en = acc ? 1u : 0u;
    asm volatile(
        "{\n\t.reg .pred p;\n\t"
        "setp.ne.u32 p, %5, 0;\n\t"
        "tcgen05.mma.cta_group::1.kind::f16 [%0], %1, %2, %3, {%4, %4, %4, %4}, p;\n\t"
        "}"
        :: "r"(d), "l"(ad), "l"(bd), "r"(idesc), "r"(0u), "r"(en)
        : "memory");
}
#endif  // __CUDA_ARCH_FEAT_SM103_ALL

// ---------------------------------------------------------------------------
// GEMM: C[M,N] = alpha * A[M,K] * B[N,K]^T (+bias), split-bf16 3-pass:
//   acc = Ah*Bh + Ah*Bl + Al*Bh      (AlBl dropped, ~2^-16 rel)
// tcgen05 path: CTA tile 256(M) x 256(N), K-chunk 32, two M=128 TMEM
//   accumulators (tmem+0, tmem+256). hi/lo interleaved per 128B smem row:
//   [hi k0-15 | hi k16-31 | lo k0-15 | lo k16-31]; desc offsets 0/2 (hi), 4/6 (lo).
//   3-stage cp.async pipeline (64KB/stage).
// grid (N/256, M/256, batch), 256 threads.
// MODE 0: f32 out (alpha)   MODE 1: split bf16 out (+bias)
// MODE 2: split bf16 transposed out (+bias), V -> Vt[b][n][s]
// ---------------------------------------------------------------------------
constexpr int TMt = 256, TNt = 256, TKt = 32;
constexpr int OFF_A = 0;
constexpr int OFF_B = 32768;
constexpr int STAGE = 65536;                       // (256+256) rows * 128B
constexpr int SMEM_TOTAL = 1024 + 3 * STAGE;       // 197632

template <int MODE>
__global__ void __launch_bounds__(256, 1) tc_gemm(
    const __nv_bfloat16* __restrict__ Ah, const __nv_bfloat16* __restrict__ Al,
    const __nv_bfloat16* __restrict__ Bh, const __nv_bfloat16* __restrict__ Bl,
    const float* __restrict__ bias,
    float* __restrict__ Cf,
    __nv_bfloat16* __restrict__ Ch, __nv_bfloat16* __restrict__ Cl,
    int K, int ldc, float alpha,
    size_t sA, size_t sB, size_t sC)
{
    extern __shared__ char smem[];
    const int tid   = threadIdx.x;
    const size_t zb = blockIdx.z;
    const int m0    = blockIdx.y * TMt;
    const int n0    = blockIdx.x * TNt;
    Ah += zb * sA;  Al += zb * sA;
    Bh += zb * sB;  Bl += zb * sB;

#if defined(__CUDA_ARCH_FEAT_SM103_ALL)
    // ======================= tcgen05 path (sm_103a) ========================
    const uint32_t sb = smem_u32(smem);

    if (tid < 32) TCGEN05_ALLOC(sb + 0, 512);
    if (tid >= 32 && tid < 64) TCGEN05_RELINQUISH();
    if (tid == 0) {
        MBARRIER_INIT(sb + 8, 1);
        MBARRIER_INIT(sb + 16, 1);
        MBARRIER_INIT(sb + 24, 1);
    }
    __syncthreads();
    uint32_t tmem;
    asm volatile("ld.shared.b32 %0, [%1];" : "=r"(tmem) : "r"(sb + 0));

    const int col = tid & 3;           // 16B unit within 64B half-row
    const int hf  = (tid >> 2) & 1;    // 0 = hi source, 1 = lo source
    const int rg  = tid >> 3;          // 0..31 base row

    const __nv_bfloat16* srcA = hf ? Al : Ah;
    const __nv_bfloat16* srcB = hf ? Bl : Bh;

    auto load_chunk = [&](int kc, int st) {
        const uint32_t base = sb + 1024 + st * STAGE;
        const size_t koff = (size_t)kc * TKt + col * 8;
        const __nv_bfloat16* pa = srcA + (size_t)(m0 + rg) * K + koff;
        const __nv_bfloat16* pb = srcB + (size_t)(n0 + rg) * K + koff;
#pragma unroll
        for (int i = 0; i < 8; ++i) {
            const uint32_t so = SWZ128((rg + 32 * i) * 128 + hf * 64 + col * 16);
            cp16(base + OFF_A + so, pa + (size_t)(32 * i) * K);
            cp16(base + OFF_B + so, pb + (size_t)(32 * i) * K);
        }
    };

    constexpr uint32_t IDESC =
        (1u << 4) | (1u << 7) | (1u << 10) | ((TNt / 8) << 17) | ((128 / 16) << 24);
    const int NC = K / TKt;

    load_chunk(0, 0); CP_COMMIT();
    load_chunk(1, 1); CP_COMMIT();
    load_chunk(2, 2); CP_COMMIT();

    int ph[3] = {0, 0, 0};
    for (int c = 0; c < NC; ++c) {
        const int st = c % 3;
        if (c + 2 < NC)      { CP_WAIT(2); }
        else if (c + 1 < NC) { CP_WAIT(1); }
        else                 { CP_WAIT(0); }
        FENCE_PROXY_ASYNC();
        __syncthreads();

        if (tid < 32 && elect_one_pred()) {
            TCGEN05_FENCE_AFTER();
            const uint32_t base = sb + 1024 + st * STAGE;
            const uint64_t daA0 = MAKE_SMEM_DESC(base + OFF_A);
            const uint64_t daA1 = MAKE_SMEM_DESC(base + OFF_A + 16384);
            const uint64_t db   = MAKE_SMEM_DESC(base + OFF_B);
#pragma unroll
            for (int half = 0; half < 2; ++half) {
                const uint64_t da = half ? daA1 : daA0;
                const uint32_t dt = tmem + half * 256;
                mma_bf16_ss(dt, da + 0, db + 0, IDESC, c != 0);   // hi*hi ks0
                mma_bf16_ss(dt, da + 2, db + 2, IDESC, true);     // hi*hi ks1
                mma_bf16_ss(dt, da + 0, db + 4, IDESC, true);     // hi*lo ks0
                mma_bf16_ss(dt, da + 2, db + 6, IDESC, true);     // hi*lo ks1
                mma_bf16_ss(dt, da + 4, db + 0, IDESC, true);     // lo*hi ks0
                mma_bf16_ss(dt, da + 6, db + 2, IDESC, true);     // lo*hi ks1
            }
            TCGEN05_COMMIT(sb + 8 + 8 * st);
        }
        MBARRIER_WAIT_PARITY(sb + 8 + 8 * st, ph[st]);
        ph[st] ^= 1;
        if (c + 3 < NC) { load_chunk(c + 3, st); CP_COMMIT(); }
    }
    TCGEN05_FENCE_AFTER();

    // epilogue: 8 warps; warps 0-3 -> D0 (rows 0-127), warps 4-7 -> D1
    {
        const int half = tid >> 7;
        const int w4   = (tid >> 5) & 3;
        const int lid  = tid & 31;
        const int m    = m0 + half * 128 + w4 * 32 + lid;
        const uint32_t dt = tmem + half * 256;
        for (int j0 = 0; j0 < TNt; j0 += 32) {
            uint32_t r[32];
            TCGEN05_LD_32X32B_X32(r, dt + j0);
            TCGEN05_WAIT_LD();
            if (MODE == 0) {
                float4* dst = (float4*)(Cf + zb * sC + (size_t)m * ldc + n0 + j0);
#pragma unroll
                for (int i = 0; i < 8; ++i) {
                    float4 v;
                    v.x = __uint_as_float(r[4 * i + 0]) * alpha;
                    v.y = __uint_as_float(r[4 * i + 1]) * alpha;
                    v.z = __uint_as_float(r[4 * i + 2]) * alpha;
                    v.w = __uint_as_float(r[4 * i + 3]) * alpha;
                    dst[i] = v;
                }
            } else if (MODE == 1) {
                const size_t rb = (size_t)m * ldc + n0 + j0;
#pragma unroll
                for (int i = 0; i < 32; i += 2) {
                    float v0 = __uint_as_float(r[i])     + bias[n0 + j0 + i];
                    float v1 = __uint_as_float(r[i + 1]) + bias[n0 + j0 + i + 1];
                    __nv_bfloat16 h0, l0, h1, l1;
                    split2(v0, h0, l0); split2(v1, h1, l1);
                    __nv_bfloat162 hp; hp.x = h0; hp.y = h1;
                    __nv_bfloat162 lp; lp.x = l0; lp.y = l1;
                    *(__nv_bfloat162*)(Ch + rb + i) = hp;
                    *(__nv_bfloat162*)(Cl + rb + i) = lp;
                }
            } else {
                const int b  = m >> 11;
                const int sx = m & 2047;
                const size_t bb = (size_t)b * DM * SEQ;
#pragma unroll
                for (int i = 0; i < 32; ++i) {
                    const int n = n0 + j0 + i;
                    float v = __uint_as_float(r[i]) + bias[n];
                    __nv_bfloat16 h, l;
                    split2(v, h, l);
                    Ch[bb + (size_t)n * SEQ + sx] = h;
                    Cl[bb + (size_t)n * SEQ + sx] = l;
                }
            }
        }
    }
    __syncthreads();
    if (tid < 32) TCGEN05_DEALLOC(tmem, 512);

#elif defined(__CUDA_ARCH__)
    // ================= mma.sync fallback (base compute_103) =================
    // Processes the 256x256 tile as four sequential 128x128 sub-tiles.
    constexpr int STR = 20;                 // words per 32-bf16 row (padded)
    constexpr int TILE_W = 128 * STR;       // 2560 words
    constexpr int STAGE_W = 4 * TILE_W;     // 10240 words
    const uint32_t sbase = smem_u32(smem);
    const int lane = tid & 31, wid = tid >> 5;
    const int wm = wid >> 1, wn = wid & 1;
    const int g = lane >> 2, tg = lane & 3;

    auto load_chunk = [&](int kc, int st, int mbase, int nbase) {
        const int q = tid & 3, r0 = tid >> 2;
        const uint32_t dst0 = sbase + st * STAGE_W * 4;
        const size_t koff = (size_t)kc * 32 + q * 8;
#pragma unroll
        for (int i = 0; i < 2; ++i) {
            const int r = r0 + 64 * i;
            const uint32_t ro = (uint32_t)(r * STR + q * 4) * 4;
            cp16(dst0 + 0 * TILE_W * 4 + ro, Ah + (size_t)(mbase + r) * K + koff);
            cp16(dst0 + 1 * TILE_W * 4 + ro, Al + (size_t)(mbase + r) * K + koff);
            cp16(dst0 + 2 * TILE_W * 4 + ro, Bh + (size_t)(nbase + r) * K + koff);
            cp16(dst0 + 3 * TILE_W * 4 + ro, Bl + (size_t)(nbase + r) * K + koff);
        }
    };

    for (int mh = 0; mh < 2; ++mh) {
        const int mb0 = m0 + mh * 128;
        for (int np = 0; np < 2; ++np) {
            const int nb0 = n0 + np * 128;

            float acc[2][8][4];
#pragma unroll
            for (int a = 0; a < 2; ++a)
#pragma unroll
                for (int b = 0; b < 8; ++b)
#pragma unroll
                    for (int c = 0; c < 4; ++c) acc[a][b][c] = 0.0f;

            const int NC = K / 32;
            load_chunk(0, 0, mb0, nb0); CP_COMMIT();

            for (int c = 0; c < NC; ++c) {
                const int st = c & 1;
                if (c + 1 < NC) { load_chunk(c + 1, st ^ 1, mb0, nb0); CP_COMMIT(); CP_WAIT(1); }
                else            { CP_WAIT(0); }
                __syncthreads();

                const uint32_t* s0 = (const uint32_t*)smem + st * STAGE_W;
#pragma unroll
                for (int ks = 0; ks < 2; ++ks) {
                    uint32_t ahf[2][4], alf[2][4];
#pragma unroll
                    for (int mt = 0; mt < 2; ++mt) {
                        const int rb = wm * 32 + mt * 16;
                        const uint32_t* pa = s0 + (rb + g) * STR + ks * 8 + tg;
                        ahf[mt][0] = pa[0];           ahf[mt][2] = pa[4];
                        ahf[mt][1] = pa[8 * STR];     ahf[mt][3] = pa[8 * STR + 4];
                        const uint32_t* pl = pa + TILE_W;
                        alf[mt][0] = pl[0];           alf[mt][2] = pl[4];
                        alf[mt][1] = pl[8 * STR];     alf[mt][3] = pl[8 * STR + 4];
                    }
#pragma unroll
                    for (int nt = 0; nt < 8; ++nt) {
                        const int nb = wn * 64 + nt * 8;
                        const uint32_t* pb = s0 + 2 * TILE_W + (nb + g) * STR + ks * 8 + tg;
                        const uint32_t bh0 = pb[0], bh1 = pb[4];
                        const uint32_t* pbl = pb + TILE_W;
                        const uint32_t bl0 = pbl[0], bl1 = pbl[4];
#pragma unroll
                        for (int mt = 0; mt < 2; ++mt) {
                            mma16816(acc[mt][nt], ahf[mt], bh0, bh1);
                            mma16816(acc[mt][nt], ahf[mt], bl0, bl1);
                            mma16816(acc[mt][nt], alf[mt], bh0, bh1);
                        }
                    }
                }
                __syncthreads();
            }

#pragma unroll
            for (int mt = 0; mt < 2; ++mt) {
#pragma unroll
                for (int nt = 0; nt < 8; ++nt) {
                    const int m1 = mb0 + wm * 32 + mt * 16 + g;
                    const int m2 = m1 + 8;
                    const int n  = nb0 + wn * 64 + nt * 8 + tg * 2;
                    const float* a = acc[mt][nt];
                    if (MODE == 0) {
                        float2 v0; v0.x = a[0] * alpha; v0.y = a[1] * alpha;
                        float2 v1; v1.x = a[2] * alpha; v1.y = a[3] * alpha;
                        *(float2*)(Cf + zb * sC + (size_t)m1 * ldc + n) = v0;
                        *(float2*)(Cf + zb * sC + (size_t)m2 * ldc + n) = v1;
                    } else if (MODE == 1) {
                        const float b0 = bias[n], b1 = bias[n + 1];
                        __nv_bfloat16 h0, l0, h1, l1;
                        split2(a[0] + b0, h0, l0); split2(a[1] + b1, h1, l1);
                        __nv_bfloat162 hp; hp.x = h0; hp.y = h1;
                        __nv_bfloat162 lp; lp.x = l0; lp.y = l1;
                        *(__nv_bfloat162*)(Ch + (size_t)m1 * ldc + n) = hp;
                        *(__nv_bfloat162*)(Cl + (size_t)m1 * ldc + n) = lp;
                        split2(a[2] + b0, h0, l0); split2(a[3] + b1, h1, l1);
                        hp.x = h0; hp.y = h1; lp.x = l0; lp.y = l1;
                        *(__nv_bfloat162*)(Ch + (size_t)m2 * ldc + n) = hp;
                        *(__nv_bfloat162*)(Cl + (size_t)m2 * ldc + n) = lp;
                    } else {
                        const float b0 = bias[n], b1 = bias[n + 1];
#pragma unroll
                        for (int e = 0; e < 4; ++e) {
                            const int m = (e < 2) ? m1 : m2;
                            const int nn = n + (e & 1);
                            const float bb_ = (e & 1) ? b1 : b0;
                            const int bidx = m >> 11, sx = m & 2047;
                            __nv_bfloat16 h, l;
                            split2(a[e] + bb_, h, l);
                            const size_t off = (size_t)bidx * DM * SEQ + (size_t)nn * SEQ + sx;
                            Ch[off] = h;
                            Cl[off] = l;
                        }
                    }
                }
            }
            __syncthreads();
        }
    }
#endif
}

// ---------------------------------------------------------------------------
// f32 -> bf16 hi/lo split
// ---------------------------------------------------------------------------
__global__ void __launch_bounds__(256) split_k(
    const float4* __restrict__ x,
    __nv_bfloat16* __restrict__ h, __nv_bfloat16* __restrict__ l, int n4)
{
    for (int i = blockIdx.x * 256 + threadIdx.x; i < n4; i += gridDim.x * 256) {
        float4 v = x[i];
        __nv_bfloat16 h0, l0, h1, l1, h2, l2, h3, l3;
        split2(v.x, h0, l0); split2(v.y, h1, l1);
        split2(v.z, h2, l2); split2(v.w, h3, l3);
        __nv_bfloat162 ha; ha.x = h0; ha.y = h1;
        __nv_bfloat162 hb; hb.x = h2; hb.y = h3;
        __nv_bfloat162 la; la.x = l0; la.y = l1;
        __nv_bfloat162 lb; lb.x = l2; lb.y = l3;
        *(__nv_bfloat162*)(h + 4 * (size_t)i)     = ha;
        *(__nv_bfloat162*)(h + 4 * (size_t)i + 2) = hb;
        *(__nv_bfloat162*)(l + 4 * (size_t)i)     = la;
        *(__nv_bfloat162*)(l + 4 * (size_t)i + 2) = lb;
    }
}

// ---------------------------------------------------------------------------
// Row softmax over SEQ, emitting split bf16 P
// ---------------------------------------------------------------------------
__global__ void __launch_bounds__(256) softmax_k(
    const float* __restrict__ S,
    __nv_bfloat16* __restrict__ Ph, __nv_bfloat16* __restrict__ Pl)
{
    const float* p = S + (size_t)blockIdx.x * SEQ;
    const int tid = threadIdx.x;

    float v[8];
    float mx = -1e30f;
#pragma unroll
    for (int i = 0; i < 8; ++i) { v[i] = p[tid + i * 256]; mx = fmaxf(mx, v[i]); }

    __shared__ float redm[8], reds[8];
#pragma unroll
    for (int o = 16; o > 0; o >>= 1)
        mx = fmaxf(mx, __shfl_xor_sync(0xffffffffu, mx, o));
    if ((tid & 31) == 0) redm[tid >> 5] = mx;
    __syncthreads();
    mx = redm[0];
#pragma unroll
    for (int i = 1; i < 8; ++i) mx = fmaxf(mx, redm[i]);

    float s = 0.0f;
#pragma unroll
    for (int i = 0; i < 8; ++i) { v[i] = __expf(v[i] - mx); s += v[i]; }
#pragma unroll
    for (int o = 16; o > 0; o >>= 1)
        s += __shfl_xor_sync(0xffffffffu, s, o);
    if ((tid & 31) == 0) reds[tid >> 5] = s;
    __syncthreads();
    s = 0.0f;
#pragma unroll
    for (int i = 0; i < 8; ++i) s += reds[i];

    const float inv = 1.0f / s;
    size_t rb = (size_t)blockIdx.x * SEQ;
#pragma unroll
    for (int i = 0; i < 8; ++i) {
        __nv_bfloat16 h, l;
        split2(v[i] * inv, h, l);
        Ph[rb + tid + i * 256] = h;
        Pl[rb + tid + i * 256] = l;
    }
}

// ---------------------------------------------------------------------------
extern "C" void kernel_launch(void* const* d_in, const int* in_sizes, int n_in,
                              void* d_out, int out_size)
{
    (void)in_sizes; (void)n_in; (void)out_size;
    const float* q  = (const float*)d_in[0];
    const float* kx = (const float*)d_in[1];
    const float* vx = (const float*)d_in[2];
    const float* Wq = (const float*)d_in[3];
    const float* bq = (const float*)d_in[4];
    const float* Wk = (const float*)d_in[5];
    const float* bk = (const float*)d_in[6];
    const float* Wv = (const float*)d_in[7];
    const float* bv = (const float*)d_in[8];
    float* out = (float*)d_out;

    __nv_bfloat16 *Xqh, *Xql, *Xkh, *Xkl, *Xvh, *Xvl;
    __nv_bfloat16 *Wqh, *Wql, *Wkh, *Wkl, *Wvh, *Wvl;
    __nv_bfloat16 *Qh, *Ql, *Kh, *Kl, *Vth, *Vtl, *Ph, *Pl;
    float* Sf;
    cudaGetSymbolAddress((void**)&Xqh, g_Xq_h); cudaGetSymbolAddress((void**)&Xql, g_Xq_l);
    cudaGetSymbolAddress((void**)&Xkh, g_Xk_h); cudaGetSymbolAddress((void**)&Xkl, g_Xk_l);
    cudaGetSymbolAddress((void**)&Xvh, g_Xv_h); cudaGetSymbolAddress((void**)&Xvl, g_Xv_l);
    cudaGetSymbolAddress((void**)&Wqh, g_Wq_h); cudaGetSymbolAddress((void**)&Wql, g_Wq_l);
    cudaGetSymbolAddress((void**)&Wkh, g_Wk_h); cudaGetSymbolAddress((void**)&Wkl, g_Wk_l);
    cudaGetSymbolAddress((void**)&Wvh, g_Wv_h); cudaGetSymbolAddress((void**)&Wvl, g_Wv_l);
    cudaGetSymbolAddress((void**)&Qh,  g_Q_h);  cudaGetSymbolAddress((void**)&Ql,  g_Q_l);
    cudaGetSymbolAddress((void**)&Kh,  g_K_h);  cudaGetSymbolAddress((void**)&Kl,  g_K_l);
    cudaGetSymbolAddress((void**)&Vth, g_Vt_h); cudaGetSymbolAddress((void**)&Vtl, g_Vt_l);
    cudaGetSymbolAddress((void**)&Ph,  g_P_h);  cudaGetSymbolAddress((void**)&Pl,  g_P_l);
    cudaGetSymbolAddress((void**)&Sf,  g_S);

    cudaFuncSetAttribute(tc_gemm<0>, cudaFuncAttributeMaxDynamicSharedMemorySize, SMEM_TOTAL);
    cudaFuncSetAttribute(tc_gemm<1>, cudaFuncAttributeMaxDynamicSharedMemorySize, SMEM_TOTAL);
    cudaFuncSetAttribute(tc_gemm<2>, cudaFuncAttributeMaxDynamicSharedMemorySize, SMEM_TOTAL);

    // 1. split inputs & weights to bf16 hi/lo
    const int nX4 = (NTOK * DIN) / 4, nW4 = (DM * DIN) / 4;
    split_k<<<4096, 256>>>((const float4*)q,  Xqh, Xql, nX4);
    split_k<<<4096, 256>>>((const float4*)kx, Xkh, Xkl, nX4);
    split_k<<<4096, 256>>>((const float4*)vx, Xvh, Xvl, nX4);
    split_k<<<1024, 256>>>((const float4*)Wq, Wqh, Wql, nW4);
    split_k<<<1024, 256>>>((const float4*)Wk, Wkh, Wkl, nW4);
    split_k<<<1024, 256>>>((const float4*)Wv, Wvh, Wvl, nW4);

    // 2. projections (epilogue: split; V transposed)
    dim3 gP(DM / TNt, NTOK / TMt, 1);
    tc_gemm<1><<<gP, 256, SMEM_TOTAL>>>(Xqh, Xql, Wqh, Wql, bq,
                                        nullptr, Qh, Ql, DIN, DM, 1.0f, 0, 0, 0);
    tc_gemm<1><<<gP, 256, SMEM_TOTAL>>>(Xkh, Xkl, Wkh, Wkl, bk,
                                        nullptr, Kh, Kl, DIN, DM, 1.0f, 0, 0, 0);
    tc_gemm<2><<<gP, 256, SMEM_TOTAL>>>(Xvh, Xvl, Wvh, Wvl, bv,
                                        nullptr, Vth, Vtl, DIN, 0, 1.0f, 0, 0, 0);

    // 3. scores S = (Q K^T) / 32, batched
    dim3 gS(SEQ / TNt, SEQ / TMt, BN);
    tc_gemm<0><<<gS, 256, SMEM_TOTAL>>>(Qh, Ql, Kh, Kl, nullptr,
                                        Sf, nullptr, nullptr, DM, SEQ, 0.03125f,
                                        (size_t)SEQ * DM, (size_t)SEQ * DM,
                                        (size_t)SEQ * SEQ);

    // 4. softmax + split
    softmax_k<<<BN * SEQ, 256>>>(Sf, Ph, Pl);

    // 5. O = P * Vt^T, batched
    dim3 gO(DM / TNt, SEQ / TMt, BN);
    tc_gemm<0><<<gO, 256, SMEM_TOTAL>>>(Ph, Pl, Vth, Vtl, nullptr,
                                        out, nullptr, nullptr, SEQ, DM, 1.0f,
                                        (size_t)SEQ * SEQ, (size_t)DM * SEQ,
                                        (size_t)SEQ * DM);
}

// round 6
// speedup vs baseline: 1.1362x; 1.1362x over previous
#include <cuda_runtime.h>
#include <cuda_bf16.h>
#include <cstdint>

// ---------------------------------------------------------------------------
// Problem constants
// ---------------------------------------------------------------------------
#define BN   8
#define SEQ  2048
#define DIN  1024
#define DM   1024
#define NTOK (BN*SEQ)          // 16384

// ---------------------------------------------------------------------------
// Scratch (__device__ globals; allocation-free rule)
// ---------------------------------------------------------------------------
__device__ __nv_bfloat16 g_Xq_h[(size_t)NTOK*DIN];
__device__ __nv_bfloat16 g_Xq_l[(size_t)NTOK*DIN];
__device__ __nv_bfloat16 g_Xk_h[(size_t)NTOK*DIN];
__device__ __nv_bfloat16 g_Xk_l[(size_t)NTOK*DIN];
__device__ __nv_bfloat16 g_Xv_h[(size_t)NTOK*DIN];
__device__ __nv_bfloat16 g_Xv_l[(size_t)NTOK*DIN];
__device__ __nv_bfloat16 g_Wq_h[(size_t)DM*DIN];
__device__ __nv_bfloat16 g_Wq_l[(size_t)DM*DIN];
__device__ __nv_bfloat16 g_Wk_h[(size_t)DM*DIN];
__device__ __nv_bfloat16 g_Wk_l[(size_t)DM*DIN];
__device__ __nv_bfloat16 g_Wv_h[(size_t)DM*DIN];
__device__ __nv_bfloat16 g_Wv_l[(size_t)DM*DIN];
__device__ __nv_bfloat16 g_Q_h [(size_t)NTOK*DM];
__device__ __nv_bfloat16 g_Q_l [(size_t)NTOK*DM];
__device__ __nv_bfloat16 g_K_h [(size_t)NTOK*DM];
__device__ __nv_bfloat16 g_K_l [(size_t)NTOK*DM];
__device__ __nv_bfloat16 g_Vt_h[(size_t)BN*DM*SEQ];     // [b][v][s]
__device__ __nv_bfloat16 g_Vt_l[(size_t)BN*DM*SEQ];
__device__ __nv_bfloat16 g_P_h[(size_t)BN*SEQ*SEQ];     // exp(scores), unnormalized
__device__ __nv_bfloat16 g_P_l[(size_t)BN*SEQ*SEQ];
__device__ float         g_rs [(size_t)BN*SEQ];         // row sums of exp

// ---------------------------------------------------------------------------
// Helpers available on base compute_103
// ---------------------------------------------------------------------------
__device__ __forceinline__ uint32_t smem_u32(const void* p) {
    uint32_t a;
    asm("{ .reg .u64 t; cvta.to.shared.u64 t, %1; cvt.u32.u64 %0, t; }"
        : "=r"(a) : "l"(p));
    return a;
}
__device__ __forceinline__ void cp16(uint32_t dst, const void* src) {
    asm volatile("cp.async.cg.shared.global [%0], [%1], 16;" :: "r"(dst), "l"(src));
}
#define CP_COMMIT()  asm volatile("cp.async.commit_group;" ::: "memory")
#define CP_WAIT(N)   asm volatile("cp.async.wait_group %0;" :: "n"(N) : "memory")

__device__ __forceinline__ void mma16816(float* c, const uint32_t* a,
                                         uint32_t b0, uint32_t b1) {
    asm volatile(
        "mma.sync.aligned.m16n8k16.row.col.f32.bf16.bf16.f32 "
        "{%0,%1,%2,%3}, {%4,%5,%6,%7}, {%8,%9}, {%0,%1,%2,%3};"
        : "+f"(c[0]), "+f"(c[1]), "+f"(c[2]), "+f"(c[3])
        : "r"(a[0]), "r"(a[1]), "r"(a[2]), "r"(a[3]), "r"(b0), "r"(b1));
}

__device__ __forceinline__ void split2(float v, __nv_bfloat16& h, __nv_bfloat16& l) {
    h = __float2bfloat16(v);
    l = __float2bfloat16(v - __bfloat162float(h));
}

// ---------------------------------------------------------------------------
// tcgen05 helpers — ONLY compiled when the build has a compute_103a pass.
// ---------------------------------------------------------------------------
#if defined(__CUDA_ARCH_FEAT_SM103_ALL)
__device__ __forceinline__ uint32_t elect_one_pred() {
    uint32_t pred;
    asm volatile(
        "{\n\t.reg .pred p;\n\t"
        "elect.sync _|p, 0xFFFFFFFF;\n\t"
        "selp.b32 %0, 1, 0, p;\n\t}"
        : "=r"(pred));
    return pred;
}
#define MBARRIER_INIT(addr, cnt) \
    asm volatile("mbarrier.init.shared.b64 [%0], %1;" :: "r"((uint32_t)(addr)), "r"((uint32_t)(cnt)) : "memory")
#define MBARRIER_WAIT_PARITY(mbar, par) do { \
    uint32_t _m = (uint32_t)(mbar), _p = (uint32_t)(par), _d; \
    asm volatile("{\n\t.reg .pred p;\n\t" \
        "mbarrier.try_wait.parity.acquire.cta.shared::cta.b64 p, [%1], %2;\n\t" \
        "selp.b32 %0, 1, 0, p;\n\t}" : "=r"(_d) : "r"(_m), "r"(_p) : "memory"); \
    if (!_d) { \
        asm volatile("{\n\t.reg .pred P1;\n\t" \
            "WL_%=:\n\t" \
            "mbarrier.try_wait.parity.acquire.cta.shared::cta.b64 P1, [%0], %1, 0x989680;\n\t" \
            "@P1 bra.uni WD_%=;\n\tbra.uni WL_%=;\n\tWD_%=:\n\t}" \
            :: "r"(_m), "r"(_p) : "memory"); \
    } \
} while (0)
#define TCGEN05_ALLOC(a, n) \
    asm volatile("tcgen05.alloc.cta_group::1.sync.aligned.shared::cta.b32 [%0], %1;" \
        :: "r"((uint32_t)(a)), "r"((uint32_t)(n)) : "memory")
#define TCGEN05_RELINQUISH() \
    asm volatile("tcgen05.relinquish_alloc_permit.cta_group::1.sync.aligned;")
#define TCGEN05_DEALLOC(t, n) \
    asm volatile("tcgen05.dealloc.cta_group::1.sync.aligned.b32 %0, %1;" :: "r"(t), "r"((uint32_t)(n)))
#define TCGEN05_COMMIT(m) \
    asm volatile("tcgen05.commit.cta_group::1.mbarrier::arrive::one.shared::cluster.b64 [%0];" \
        :: "r"((uint32_t)(m)) : "memory")
#define TCGEN05_WAIT_LD()    asm volatile("tcgen05.wait::ld.sync.aligned;" ::: "memory")
#define TCGEN05_FENCE_AFTER() asm volatile("tcgen05.fence::after_thread_sync;" ::: "memory")
#define FENCE_PROXY_ASYNC()  asm volatile("fence.proxy.async.shared::cta;" ::: "memory")
#define TCGEN05_LD_32X32B_X32(r, ta) \
    asm volatile( \
        "tcgen05.ld.sync.aligned.32x32b.x32.b32 " \
        "{%0, %1, %2, %3, %4, %5, %6, %7, " \
        " %8, %9, %10, %11, %12, %13, %14, %15, " \
        " %16, %17, %18, %19, %20, %21, %22, %23, " \
        " %24, %25, %26, %27, %28, %29, %30, %31}, [%32];" \
        : "=r"((r)[0]),  "=r"((r)[1]),  "=r"((r)[2]),  "=r"((r)[3]), \
          "=r"((r)[4]),  "=r"((r)[5]),  "=r"((r)[6]),  "=r"((r)[7]), \
          "=r"((r)[8]),  "=r"((r)[9]),  "=r"((r)[10]), "=r"((r)[11]), \
          "=r"((r)[12]), "=r"((r)[13]), "=r"((r)[14]), "=r"((r)[15]), \
          "=r"((r)[16]), "=r"((r)[17]), "=r"((r)[18]), "=r"((r)[19]), \
          "=r"((r)[20]), "=r"((r)[21]), "=r"((r)[22]), "=r"((r)[23]), \
          "=r"((r)[24]), "=r"((r)[25]), "=r"((r)[26]), "=r"((r)[27]), \
          "=r"((r)[28]), "=r"((r)[29]), "=r"((r)[30]), "=r"((r)[31]) \
        : "r"(ta))
static constexpr uint64_t SMEM_DESC_BASE_SW128 =
    (uint64_t(2)  << 61) | (uint64_t(1) << 46) | (uint64_t(64) << 32) | (uint64_t(1) << 16);
#define MAKE_SMEM_DESC(ba) (SMEM_DESC_BASE_SW128 | ((uint64_t)((ba) >> 4) & 0x3FFF))
#define SWZ128(off) ((off) ^ (((off) >> 3) & 0x70))
__device__ __forceinline__ void mma_bf16_ss(uint32_t d, uint64_t ad, uint64_t bd,
                                            uint32_t idesc, bool acc) {
    uint32_t en = acc ? 1u : 0u;
    asm volatile(
        "{\n\t.reg .pred p;\n\t"
        "setp.ne.u32 p, %5, 0;\n\t"
        "tcgen05.mma.cta_group::1.kind::f16 [%0], %1, %2, %3, {%4, %4, %4, %4}, p;\n\t"
        "}"
        :: "r"(d), "l"(ad), "l"(bd), "r"(idesc), "r"(0u), "r"(en)
        : "memory");
}
#endif  // __CUDA_ARCH_FEAT_SM103_ALL

// ---------------------------------------------------------------------------
// GEMM: C[M,N] = A[M,K] * B[N,K]^T, split-bf16 3-pass (Ah*Bh + Ah*Bl + Al*Bh).
// tcgen05: CTA tile 256x256, K-chunk 32, two M=128 TMEM accumulators,
//   hi/lo interleaved per 128B smem row, 3-stage cp.async pipeline with the
//   MMA-completion wait DEFERRED one chunk (MMA(c) overlaps iteration c+1).
// grid (N/256, M/256, batch), 256 threads.
// MODE 1: split bf16 out (+bias)            [Q,K proj]
// MODE 2: split bf16 transposed out (+bias) [V proj -> Vt[b][n][s]]
// MODE 3: e=expf(acc*alpha) -> split bf16 out + row-sum atomics  [scores]
// MODE 4: f32 out = acc / rowsum[m]         [PV]
// ---------------------------------------------------------------------------
constexpr int TMt = 256, TNt = 256, TKt = 32;
constexpr int OFF_A = 0;
constexpr int OFF_B = 32768;
constexpr int STAGE = 65536;                       // (256+256) rows * 128B
constexpr int SMEM_TOTAL = 1024 + 3 * STAGE;       // 197632

template <int MODE>
__global__ void __launch_bounds__(256, 1) tc_gemm(
    const __nv_bfloat16* __restrict__ Ah, const __nv_bfloat16* __restrict__ Al,
    const __nv_bfloat16* __restrict__ Bh, const __nv_bfloat16* __restrict__ Bl,
    const float* __restrict__ bias,
    float* __restrict__ Cf,
    __nv_bfloat16* __restrict__ Ch, __nv_bfloat16* __restrict__ Cl,
    float* __restrict__ rs,
    int K, int ldc, float alpha,
    size_t sA, size_t sB, size_t sC)
{
    extern __shared__ char smem[];
    const int tid   = threadIdx.x;
    const size_t zb = blockIdx.z;
    const int m0    = blockIdx.y * TMt;
    const int n0    = blockIdx.x * TNt;
    Ah += zb * sA;  Al += zb * sA;
    Bh += zb * sB;  Bl += zb * sB;

#if defined(__CUDA_ARCH_FEAT_SM103_ALL)
    // ======================= tcgen05 path (sm_103a) ========================
    const uint32_t sb = smem_u32(smem);

    if (tid < 32) TCGEN05_ALLOC(sb + 0, 512);
    if (tid >= 32 && tid < 64) TCGEN05_RELINQUISH();
    if (tid == 0) {
        MBARRIER_INIT(sb + 8, 1);
        MBARRIER_INIT(sb + 16, 1);
        MBARRIER_INIT(sb + 24, 1);
    }
    __syncthreads();
    uint32_t tmem;
    asm volatile("ld.shared.b32 %0, [%1];" : "=r"(tmem) : "r"(sb + 0));

    const int col = tid & 3;           // 16B unit within 64B half-row
    const int hf  = (tid >> 2) & 1;    // 0 = hi source, 1 = lo source
    const int rg  = tid >> 3;          // 0..31 base row

    const __nv_bfloat16* srcA = hf ? Al : Ah;
    const __nv_bfloat16* srcB = hf ? Bl : Bh;

    auto load_chunk = [&](int kc, int st) {
        const uint32_t base = sb + 1024 + st * STAGE;
        const size_t koff = (size_t)kc * TKt + col * 8;
        const __nv_bfloat16* pa = srcA + (size_t)(m0 + rg) * K + koff;
        const __nv_bfloat16* pb = srcB + (size_t)(n0 + rg) * K + koff;
#pragma unroll
        for (int i = 0; i < 8; ++i) {
            const uint32_t so = SWZ128((rg + 32 * i) * 128 + hf * 64 + col * 16);
            cp16(base + OFF_A + so, pa + (size_t)(32 * i) * K);
            cp16(base + OFF_B + so, pb + (size_t)(32 * i) * K);
        }
    };

    constexpr uint32_t IDESC =
        (1u << 4) | (1u << 7) | (1u << 10) | ((TNt / 8) << 17) | ((128 / 16) << 24);
    const int NC = K / TKt;

    load_chunk(0, 0); CP_COMMIT();
    load_chunk(1, 1); CP_COMMIT();

    int ph[3] = {0, 0, 0};
    for (int c = 0; c < NC; ++c) {
        const int st = c % 3;
        CP_WAIT(1);                    // chunk c resident (chunk c+1 may be in flight)
        FENCE_PROXY_ASYNC();
        __syncthreads();

        if (tid < 32 && elect_one_pred()) {
            TCGEN05_FENCE_AFTER();
            const uint32_t base = sb + 1024 + st * STAGE;
            const uint64_t daA0 = MAKE_SMEM_DESC(base + OFF_A);
            const uint64_t daA1 = MAKE_SMEM_DESC(base + OFF_A + 16384);
            const uint64_t db   = MAKE_SMEM_DESC(base + OFF_B);
#pragma unroll
            for (int half = 0; half < 2; ++half) {
                const uint64_t da = half ? daA1 : daA0;
                const uint32_t dt = tmem + half * 256;
                mma_bf16_ss(dt, da + 0, db + 0, IDESC, c != 0);   // hi*hi ks0
                mma_bf16_ss(dt, da + 2, db + 2, IDESC, true);     // hi*hi ks1
                mma_bf16_ss(dt, da + 0, db + 4, IDESC, true);     // hi*lo ks0
                mma_bf16_ss(dt, da + 2, db + 6, IDESC, true);     // hi*lo ks1
                mma_bf16_ss(dt, da + 4, db + 0, IDESC, true);     // lo*hi ks0
                mma_bf16_ss(dt, da + 6, db + 2, IDESC, true);     // lo*hi ks1
            }
            TCGEN05_COMMIT(sb + 8 + 8 * st);
        }

        // Deferred wait: MMA(c-1) frees stage (c-1)%3 == (c+2)%3, which the
        // upcoming load needs. MMA(c) keeps running into the next iteration.
        if (c > 0) {
            const int sp = (c - 1) % 3;
            MBARRIER_WAIT_PARITY(sb + 8 + 8 * sp, ph[sp]);
            ph[sp] ^= 1;
        }
        if (c + 2 < NC) { load_chunk(c + 2, (c + 2) % 3); CP_COMMIT(); }
    }
    {
        const int sl = (NC - 1) % 3;
        MBARRIER_WAIT_PARITY(sb + 8 + 8 * sl, ph[sl]);
    }
    TCGEN05_FENCE_AFTER();

    // epilogue: warps 0-3 -> D0 (rows 0-127), warps 4-7 -> D1 (rows 128-255)
    {
        const int half = tid >> 7;
        const int w4   = (tid >> 5) & 3;
        const int lid  = tid & 31;
        const int m    = m0 + half * 128 + w4 * 32 + lid;
        const uint32_t dt = tmem + half * 256;
        float inv = 1.0f, lsum = 0.0f;
        if (MODE == 4) inv = 1.0f / rs[zb * SEQ + m];
        for (int j0 = 0; j0 < TNt; j0 += 32) {
            uint32_t r[32];
            TCGEN05_LD_32X32B_X32(r, dt + j0);
            TCGEN05_WAIT_LD();
            if (MODE == 4) {
                float4* dst = (float4*)(Cf + zb * sC + (size_t)m * ldc + n0 + j0);
#pragma unroll
                for (int i = 0; i < 8; ++i) {
                    float4 v;
                    v.x = __uint_as_float(r[4 * i + 0]) * inv;
                    v.y = __uint_as_float(r[4 * i + 1]) * inv;
                    v.z = __uint_as_float(r[4 * i + 2]) * inv;
                    v.w = __uint_as_float(r[4 * i + 3]) * inv;
                    dst[i] = v;
                }
            } else if (MODE == 1 || MODE == 3) {
                const size_t rb = (MODE == 3 ? zb * (size_t)SEQ * SEQ : 0)
                                + (size_t)m * ldc + n0 + j0;
#pragma unroll
                for (int i = 0; i < 32; i += 2) {
                    float v0, v1;
                    if (MODE == 3) {
                        v0 = __expf(__uint_as_float(r[i])     * alpha);
                        v1 = __expf(__uint_as_float(r[i + 1]) * alpha);
                        lsum += v0 + v1;
                    } else {
                        v0 = __uint_as_float(r[i])     + bias[n0 + j0 + i];
                        v1 = __uint_as_float(r[i + 1]) + bias[n0 + j0 + i + 1];
                    }
                    __nv_bfloat16 h0, l0, h1, l1;
                    split2(v0, h0, l0); split2(v1, h1, l1);
                    __nv_bfloat162 hp; hp.x = h0; hp.y = h1;
                    __nv_bfloat162 lp; lp.x = l0; lp.y = l1;
                    *(__nv_bfloat162*)(Ch + rb + i) = hp;
                    *(__nv_bfloat162*)(Cl + rb + i) = lp;
                }
            } else {  // MODE 2
                const int b  = m >> 11;
                const int sx = m & 2047;
                const size_t bb = (size_t)b * DM * SEQ;
#pragma unroll
                for (int i = 0; i < 32; ++i) {
                    const int n = n0 + j0 + i;
                    float v = __uint_as_float(r[i]) + bias[n];
                    __nv_bfloat16 h, l;
                    split2(v, h, l);
                    Ch[bb + (size_t)n * SEQ + sx] = h;
                    Cl[bb + (size_t)n * SEQ + sx] = l;
                }
            }
        }
        if (MODE == 3) atomicAdd(&rs[zb * SEQ + m], lsum);
    }
    __syncthreads();
    if (tid < 32) TCGEN05_DEALLOC(tmem, 512);

#elif defined(__CUDA_ARCH__)
    // ================= mma.sync fallback (base compute_103) =================
    // Processes the 256x256 tile as four sequential 128x128 sub-tiles.
    constexpr int STR = 20;
    constexpr int TILE_W = 128 * STR;
    constexpr int STAGE_W = 4 * TILE_W;
    const uint32_t sbase = smem_u32(smem);
    const int lane = tid & 31, wid = tid >> 5;
    const int wm = wid >> 1, wn = wid & 1;
    const int g = lane >> 2, tg = lane & 3;

    auto load_chunk = [&](int kc, int st, int mbase, int nbase) {
        const int q = tid & 3, r0 = tid >> 2;
        const uint32_t dst0 = sbase + st * STAGE_W * 4;
        const size_t koff = (size_t)kc * 32 + q * 8;
#pragma unroll
        for (int i = 0; i < 2; ++i) {
            const int r = r0 + 64 * i;
            const uint32_t ro = (uint32_t)(r * STR + q * 4) * 4;
            cp16(dst0 + 0 * TILE_W * 4 + ro, Ah + (size_t)(mbase + r) * K + koff);
            cp16(dst0 + 1 * TILE_W * 4 + ro, Al + (size_t)(mbase + r) * K + koff);
            cp16(dst0 + 2 * TILE_W * 4 + ro, Bh + (size_t)(nbase + r) * K + koff);
            cp16(dst0 + 3 * TILE_W * 4 + ro, Bl + (size_t)(nbase + r) * K + koff);
        }
    };

    for (int mh = 0; mh < 2; ++mh) {
        const int mb0 = m0 + mh * 128;
        for (int np = 0; np < 2; ++np) {
            const int nb0 = n0 + np * 128;

            float acc[2][8][4];
#pragma unroll
            for (int a = 0; a < 2; ++a)
#pragma unroll
                for (int b = 0; b < 8; ++b)
#pragma unroll
                    for (int c = 0; c < 4; ++c) acc[a][b][c] = 0.0f;

            const int NC = K / 32;
            load_chunk(0, 0, mb0, nb0); CP_COMMIT();

            for (int c = 0; c < NC; ++c) {
                const int st = c & 1;
                if (c + 1 < NC) { load_chunk(c + 1, st ^ 1, mb0, nb0); CP_COMMIT(); CP_WAIT(1); }
                else            { CP_WAIT(0); }
                __syncthreads();

                const uint32_t* s0 = (const uint32_t*)smem + st * STAGE_W;
#pragma unroll
                for (int ks = 0; ks < 2; ++ks) {
                    uint32_t ahf[2][4], alf[2][4];
#pragma unroll
                    for (int mt = 0; mt < 2; ++mt) {
                        const int rb = wm * 32 + mt * 16;
                        const uint32_t* pa = s0 + (rb + g) * STR + ks * 8 + tg;
                        ahf[mt][0] = pa[0];           ahf[mt][2] = pa[4];
                        ahf[mt][1] = pa[8 * STR];     ahf[mt][3] = pa[8 * STR + 4];
                        const uint32_t* pl = pa + TILE_W;
                        alf[mt][0] = pl[0];           alf[mt][2] = pl[4];
                        alf[mt][1] = pl[8 * STR];     alf[mt][3] = pl[8 * STR + 4];
                    }
#pragma unroll
                    for (int nt = 0; nt < 8; ++nt) {
                        const int nb = wn * 64 + nt * 8;
                        const uint32_t* pb = s0 + 2 * TILE_W + (nb + g) * STR + ks * 8 + tg;
                        const uint32_t bh0 = pb[0], bh1 = pb[4];
                        const uint32_t* pbl = pb + TILE_W;
                        const uint32_t bl0 = pbl[0], bl1 = pbl[4];
#pragma unroll
                        for (int mt = 0; mt < 2; ++mt) {
                            mma16816(acc[mt][nt], ahf[mt], bh0, bh1);
                            mma16816(acc[mt][nt], ahf[mt], bl0, bl1);
                            mma16816(acc[mt][nt], alf[mt], bh0, bh1);
                        }
                    }
                }
                __syncthreads();
            }

#pragma unroll
            for (int mt = 0; mt < 2; ++mt) {
#pragma unroll
                for (int nt = 0; nt < 8; ++nt) {
                    const int m1 = mb0 + wm * 32 + mt * 16 + g;
                    const int m2 = m1 + 8;
                    const int n  = nb0 + wn * 64 + nt * 8 + tg * 2;
                    const float* a = acc[mt][nt];
                    if (MODE == 4) {
                        const float i1 = 1.0f / rs[zb * SEQ + m1];
                        const float i2 = 1.0f / rs[zb * SEQ + m2];
                        float2 v0; v0.x = a[0] * i1; v0.y = a[1] * i1;
                        float2 v1; v1.x = a[2] * i2; v1.y = a[3] * i2;
                        *(float2*)(Cf + zb * sC + (size_t)m1 * ldc + n) = v0;
                        *(float2*)(Cf + zb * sC + (size_t)m2 * ldc + n) = v1;
                    } else if (MODE == 1 || MODE == 3) {
                        const size_t ob = (MODE == 3 ? zb * (size_t)SEQ * SEQ : 0);
                        float e0, e1, e2, e3;
                        if (MODE == 3) {
                            e0 = __expf(a[0] * alpha); e1 = __expf(a[1] * alpha);
                            e2 = __expf(a[2] * alpha); e3 = __expf(a[3] * alpha);
                            atomicAdd(&rs[zb * SEQ + m1], e0 + e1);
                            atomicAdd(&rs[zb * SEQ + m2], e2 + e3);
                        } else {
                            const float b0 = bias[n], b1 = bias[n + 1];
                            e0 = a[0] + b0; e1 = a[1] + b1;
                            e2 = a[2] + b0; e3 = a[3] + b1;
                        }
                        __nv_bfloat16 h0, l0, h1, l1;
                        split2(e0, h0, l0); split2(e1, h1, l1);
                        __nv_bfloat162 hp; hp.x = h0; hp.y = h1;
                        __nv_bfloat162 lp; lp.x = l0; lp.y = l1;
                        *(__nv_bfloat162*)(Ch + ob + (size_t)m1 * ldc + n) = hp;
                        *(__nv_bfloat162*)(Cl + ob + (size_t)m1 * ldc + n) = lp;
                        split2(e2, h0, l0); split2(e3, h1, l1);
                        hp.x = h0; hp.y = h1; lp.x = l0; lp.y = l1;
                        *(__nv_bfloat162*)(Ch + ob + (size_t)m2 * ldc + n) = hp;
                        *(__nv_bfloat162*)(Cl + ob + (size_t)m2 * ldc + n) = lp;
                    } else {  // MODE 2
                        const float b0 = bias[n], b1 = bias[n + 1];
#pragma unroll
                        for (int e = 0; e < 4; ++e) {
                            const int m = (e < 2) ? m1 : m2;
                            const int nn = n + (e & 1);
                            const float bb_ = (e & 1) ? b1 : b0;
                            const int bidx = m >> 11, sx = m & 2047;
                            __nv_bfloat16 h, l;
                            split2(a[e] + bb_, h, l);
                            const size_t off = (size_t)bidx * DM * SEQ + (size_t)nn * SEQ + sx;
                            Ch[off] = h;
                            Cl[off] = l;
                        }
                    }
                }
            }
            __syncthreads();
        }
    }
#endif
}

// ---------------------------------------------------------------------------
// f32 -> bf16 hi/lo split
// ---------------------------------------------------------------------------
__global__ void __launch_bounds__(256) split_k(
    const float4* __restrict__ x,
    __nv_bfloat16* __restrict__ h, __nv_bfloat16* __restrict__ l, int n4)
{
    for (int i = blockIdx.x * 256 + threadIdx.x; i < n4; i += gridDim.x * 256) {
        float4 v = x[i];
        __nv_bfloat16 h0, l0, h1, l1, h2, l2, h3, l3;
        split2(v.x, h0, l0); split2(v.y, h1, l1);
        split2(v.z, h2, l2); split2(v.w, h3, l3);
        __nv_bfloat162 ha; ha.x = h0; ha.y = h1;
        __nv_bfloat162 hb; hb.x = h2; hb.y = h3;
        __nv_bfloat162 la; la.x = l0; la.y = l1;
        __nv_bfloat162 lb; lb.x = l2; lb.y = l3;
        *(__nv_bfloat162*)(h + 4 * (size_t)i)     = ha;
        *(__nv_bfloat162*)(h + 4 * (size_t)i + 2) = hb;
        *(__nv_bfloat162*)(l + 4 * (size_t)i)     = la;
        *(__nv_bfloat162*)(l + 4 * (size_t)i + 2) = lb;
    }
}

// ---------------------------------------------------------------------------
// zero the row-sum accumulator
// ---------------------------------------------------------------------------
__global__ void __launch_bounds__(1024) zero_k(float* __restrict__ p, int n)
{
    int i = blockIdx.x * 1024 + threadIdx.x;
    if (i < n) p[i] = 0.0f;
}

// ---------------------------------------------------------------------------
extern "C" void kernel_launch(void* const* d_in, const int* in_sizes, int n_in,
                              void* d_out, int out_size)
{
    (void)in_sizes; (void)n_in; (void)out_size;
    const float* q  = (const float*)d_in[0];
    const float* kx = (const float*)d_in[1];
    const float* vx = (const float*)d_in[2];
    const float* Wq = (const float*)d_in[3];
    const float* bq = (const float*)d_in[4];
    const float* Wk = (const float*)d_in[5];
    const float* bk = (const float*)d_in[6];
    const float* Wv = (const float*)d_in[7];
    const float* bv = (const float*)d_in[8];
    float* out = (float*)d_out;

    __nv_bfloat16 *Xqh, *Xql, *Xkh, *Xkl, *Xvh, *Xvl;
    __nv_bfloat16 *Wqh, *Wql, *Wkh, *Wkl, *Wvh, *Wvl;
    __nv_bfloat16 *Qh, *Ql, *Kh, *Kl, *Vth, *Vtl, *Ph, *Pl;
    float* rs;
    cudaGetSymbolAddress((void**)&Xqh, g_Xq_h); cudaGetSymbolAddress((void**)&Xql, g_Xq_l);
    cudaGetSymbolAddress((void**)&Xkh, g_Xk_h); cudaGetSymbolAddress((void**)&Xkl, g_Xk_l);
    cudaGetSymbolAddress((void**)&Xvh, g_Xv_h); cudaGetSymbolAddress((void**)&Xvl, g_Xv_l);
    cudaGetSymbolAddress((void**)&Wqh, g_Wq_h); cudaGetSymbolAddress((void**)&Wql, g_Wq_l);
    cudaGetSymbolAddress((void**)&Wkh, g_Wk_h); cudaGetSymbolAddress((void**)&Wkl, g_Wk_l);
    cudaGetSymbolAddress((void**)&Wvh, g_Wv_h); cudaGetSymbolAddress((void**)&Wvl, g_Wv_l);
    cudaGetSymbolAddress((void**)&Qh,  g_Q_h);  cudaGetSymbolAddress((void**)&Ql,  g_Q_l);
    cudaGetSymbolAddress((void**)&Kh,  g_K_h);  cudaGetSymbolAddress((void**)&Kl,  g_K_l);
    cudaGetSymbolAddress((void**)&Vth, g_Vt_h); cudaGetSymbolAddress((void**)&Vtl, g_Vt_l);
    cudaGetSymbolAddress((void**)&Ph,  g_P_h);  cudaGetSymbolAddress((void**)&Pl,  g_P_l);
    cudaGetSymbolAddress((void**)&rs,  g_rs);

    cudaFuncSetAttribute(tc_gemm<1>, cudaFuncAttributeMaxDynamicSharedMemorySize, SMEM_TOTAL);
    cudaFuncSetAttribute(tc_gemm<2>, cudaFuncAttributeMaxDynamicSharedMemorySize, SMEM_TOTAL);
    cudaFuncSetAttribute(tc_gemm<3>, cudaFuncAttributeMaxDynamicSharedMemorySize, SMEM_TOTAL);
    cudaFuncSetAttribute(tc_gemm<4>, cudaFuncAttributeMaxDynamicSharedMemorySize, SMEM_TOTAL);

    // 1. split inputs & weights to bf16 hi/lo; zero row sums
    const int nX4 = (NTOK * DIN) / 4, nW4 = (DM * DIN) / 4;
    split_k<<<4096, 256>>>((const float4*)q,  Xqh, Xql, nX4);
    split_k<<<4096, 256>>>((const float4*)kx, Xkh, Xkl, nX4);
    split_k<<<4096, 256>>>((const float4*)vx, Xvh, Xvl, nX4);
    split_k<<<1024, 256>>>((const float4*)Wq, Wqh, Wql, nW4);
    split_k<<<1024, 256>>>((const float4*)Wk, Wkh, Wkl, nW4);
    split_k<<<1024, 256>>>((const float4*)Wv, Wvh, Wvl, nW4);
    zero_k<<<(BN * SEQ + 1023) / 1024, 1024>>>(rs, BN * SEQ);

    // 2. projections (epilogue: split; V transposed)
    dim3 gP(DM / TNt, NTOK / TMt, 1);
    tc_gemm<1><<<gP, 256, SMEM_TOTAL>>>(Xqh, Xql, Wqh, Wql, bq,
                                        nullptr, Qh, Ql, nullptr,
                                        DIN, DM, 1.0f, 0, 0, 0);
    tc_gemm<1><<<gP, 256, SMEM_TOTAL>>>(Xkh, Xkl, Wkh, Wkl, bk,
                                        nullptr, Kh, Kl, nullptr,
                                        DIN, DM, 1.0f, 0, 0, 0);
    tc_gemm<2><<<gP, 256, SMEM_TOTAL>>>(Xvh, Xvl, Wvh, Wvl, bv,
                                        nullptr, Vth, Vtl, nullptr,
                                        DIN, 0, 1.0f, 0, 0, 0);

    // 3. scores + exp + row sums (no separate softmax pass)
    dim3 gS(SEQ / TNt, SEQ / TMt, BN);
    tc_gemm<3><<<gS, 256, SMEM_TOTAL>>>(Qh, Ql, Kh, Kl, nullptr,
                                        nullptr, Ph, Pl, rs,
                                        DM, SEQ, 0.03125f,
                                        (size_t)SEQ * DM, (size_t)SEQ * DM, 0);

    // 4. O = (P * Vt^T) / rowsum, batched
    dim3 gO(DM / TNt, SEQ / TMt, BN);
    tc_gemm<4><<<gO, 256, SMEM_TOTAL>>>(Ph, Pl, Vth, Vtl, nullptr,
                                        out, nullptr, nullptr, rs,
                                        SEQ, DM, 1.0f,
                                        (size_t)SEQ * SEQ, (size_t)DM * SEQ,
                                        (size_t)SEQ * DM);
}

// round 7
// speedup vs baseline: 1.7855x; 1.5715x over previous
#include <cuda_runtime.h>
#include <cuda_bf16.h>
#include <cstdint>

// ---------------------------------------------------------------------------
// Problem constants
// ---------------------------------------------------------------------------
#define BN   8
#define SEQ  2048
#define DIN  1024
#define DM   1024
#define NTOK (BN*SEQ)          // 16384

// ---------------------------------------------------------------------------
// Blocked-operand layout:
//   operand[row, k] stored as 32KB blocks indexed [row/256][k/32] (k-chunk kc).
//   Inside a block: 256 rows x 128B; row image = [hi k0..31 (64B) | lo k0..31],
//   SW128-swizzled: byte off' = off ^ ((off>>3)&0x70). This is byte-for-byte
//   the SMEM image the tcgen05 mainloop consumed in round 6, so each GEMM
//   chunk load is TWO contiguous 32KB cp.async.bulk copies.
// ---------------------------------------------------------------------------
#define SWZ128(off) ((off) ^ (((off) >> 3) & 0x70))

// Scratch (__device__ globals; allocation-free rule). All blocked operands are
// byte arrays: elems * 4 bytes (2B hi + 2B lo).
__device__ uint8_t g_Xq[(size_t)NTOK*DIN*4];
__device__ uint8_t g_Xk[(size_t)NTOK*DIN*4];
__device__ uint8_t g_Xv[(size_t)NTOK*DIN*4];
__device__ uint8_t g_Wq[(size_t)DM*DIN*4];
__device__ uint8_t g_Wk[(size_t)DM*DIN*4];
__device__ uint8_t g_Wv[(size_t)DM*DIN*4];
__device__ uint8_t g_Qb[(size_t)NTOK*DM*4];          // per-batch blocks, stride 8MB
__device__ uint8_t g_Kb[(size_t)NTOK*DM*4];
__device__ uint8_t g_Vt[(size_t)BN*DM*SEQ*4];        // rows=v, k=s, stride 8MB
__device__ uint8_t g_Pb[(size_t)BN*SEQ*SEQ*4];       // rows=q, k=s, stride 16MB
__device__ float   g_rs[(size_t)BN*SEQ];

// ---------------------------------------------------------------------------
// Helpers available on base compute_103
// ---------------------------------------------------------------------------
__device__ __forceinline__ uint32_t smem_u32(const void* p) {
    uint32_t a;
    asm("{ .reg .u64 t; cvta.to.shared.u64 t, %1; cvt.u32.u64 %0, t; }"
        : "=r"(a) : "l"(p));
    return a;
}
__device__ __forceinline__ void cp16(uint32_t dst, const void* src) {
    asm volatile("cp.async.cg.shared.global [%0], [%1], 16;" :: "r"(dst), "l"(src));
}
#define CP_COMMIT()  asm volatile("cp.async.commit_group;" ::: "memory")
#define CP_WAIT(N)   asm volatile("cp.async.wait_group %0;" :: "n"(N) : "memory")

__device__ __forceinline__ void mma16816(float* c, const uint32_t* a,
                                         uint32_t b0, uint32_t b1) {
    asm volatile(
        "mma.sync.aligned.m16n8k16.row.col.f32.bf16.bf16.f32 "
        "{%0,%1,%2,%3}, {%4,%5,%6,%7}, {%8,%9}, {%0,%1,%2,%3};"
        : "+f"(c[0]), "+f"(c[1]), "+f"(c[2]), "+f"(c[3])
        : "r"(a[0]), "r"(a[1]), "r"(a[2]), "r"(a[3]), "r"(b0), "r"(b1));
}

__device__ __forceinline__ void split2(float v, __nv_bfloat16& h, __nv_bfloat16& l) {
    h = __float2bfloat16(v);
    l = __float2bfloat16(v - __bfloat162float(h));
}
__device__ __forceinline__ uint32_t pkbf2(__nv_bfloat16 a, __nv_bfloat16 b) {
    __nv_bfloat162 t; t.x = a; t.y = b;
    return *(uint32_t*)&t;
}
// scalar hi/lo store into blocked layout (fallback path / Vt scatter)
__device__ __forceinline__ void store_blk2(uint8_t* base, int row, int k,
                                           int nkc, float v) {
    const size_t blk = (((size_t)(row >> 8)) * nkc + (k >> 5)) << 15;
    const uint32_t off = (uint32_t)(row & 255) * 128 + ((k & 31) >> 3) * 16 + (k & 7) * 2;
    __nv_bfloat16 h, l;
    split2(v, h, l);
    *(__nv_bfloat16*)(base + blk + SWZ128(off))      = h;
    *(__nv_bfloat16*)(base + blk + SWZ128(off + 64)) = l;
}

// bulk copy (UBLKCP): contiguous gmem -> smem, completion via mbarrier tx-bytes
__device__ __forceinline__ void bulk_ld(uint32_t dst, const void* src,
                                        uint32_t bytes, uint32_t mbar) {
    asm volatile(
        "cp.async.bulk.shared::cluster.global.mbarrier::complete_tx::bytes "
        "[%0], [%1], %2, [%3];"
        :: "r"(dst), "l"(src), "r"(bytes), "r"(mbar) : "memory");
}
#define MBAR_INIT(addr, cnt) \
    asm volatile("mbarrier.init.shared.b64 [%0], %1;" :: "r"((uint32_t)(addr)), "r"((uint32_t)(cnt)) : "memory")
#define MBAR_EXPECT(addr, tx) \
    asm volatile("mbarrier.arrive.expect_tx.shared.b64 _, [%0], %1;" :: "r"((uint32_t)(addr)), "r"((uint32_t)(tx)) : "memory")
#define MBAR_WAIT(mbar, par) do { \
    uint32_t _m = (uint32_t)(mbar), _p = (uint32_t)(par), _d; \
    asm volatile("{\n\t.reg .pred p;\n\t" \
        "mbarrier.try_wait.parity.acquire.cta.shared::cta.b64 p, [%1], %2;\n\t" \
        "selp.b32 %0, 1, 0, p;\n\t}" : "=r"(_d) : "r"(_m), "r"(_p) : "memory"); \
    if (!_d) { \
        asm volatile("{\n\t.reg .pred P1;\n\t" \
            "WL_%=:\n\t" \
            "mbarrier.try_wait.parity.acquire.cta.shared::cta.b64 P1, [%0], %1, 0x989680;\n\t" \
            "@P1 bra.uni WD_%=;\n\tbra.uni WL_%=;\n\tWD_%=:\n\t}" \
            :: "r"(_m), "r"(_p) : "memory"); \
    } \
} while (0)

// ---------------------------------------------------------------------------
// tcgen05 helpers — ONLY compiled when the build has a compute_103a pass.
// ---------------------------------------------------------------------------
#if defined(__CUDA_ARCH_FEAT_SM103_ALL)
__device__ __forceinline__ uint32_t elect_one_pred() {
    uint32_t pred;
    asm volatile(
        "{\n\t.reg .pred p;\n\t"
        "elect.sync _|p, 0xFFFFFFFF;\n\t"
        "selp.b32 %0, 1, 0, p;\n\t}"
        : "=r"(pred));
    return pred;
}
#define TCGEN05_ALLOC(a, n) \
    asm volatile("tcgen05.alloc.cta_group::1.sync.aligned.shared::cta.b32 [%0], %1;" \
        :: "r"((uint32_t)(a)), "r"((uint32_t)(n)) : "memory")
#define TCGEN05_RELINQUISH() \
    asm volatile("tcgen05.relinquish_alloc_permit.cta_group::1.sync.aligned;")
#define TCGEN05_DEALLOC(t, n) \
    asm volatile("tcgen05.dealloc.cta_group::1.sync.aligned.b32 %0, %1;" :: "r"(t), "r"((uint32_t)(n)))
#define TCGEN05_COMMIT(m) \
    asm volatile("tcgen05.commit.cta_group::1.mbarrier::arrive::one.shared::cluster.b64 [%0];" \
        :: "r"((uint32_t)(m)) : "memory")
#define TCGEN05_WAIT_LD()    asm volatile("tcgen05.wait::ld.sync.aligned;" ::: "memory")
#define TCGEN05_FENCE_AFTER() asm volatile("tcgen05.fence::after_thread_sync;" ::: "memory")
#define TCGEN05_LD_32X32B_X32(r, ta) \
    asm volatile( \
        "tcgen05.ld.sync.aligned.32x32b.x32.b32 " \
        "{%0, %1, %2, %3, %4, %5, %6, %7, " \
        " %8, %9, %10, %11, %12, %13, %14, %15, " \
        " %16, %17, %18, %19, %20, %21, %22, %23, " \
        " %24, %25, %26, %27, %28, %29, %30, %31}, [%32];" \
        : "=r"((r)[0]),  "=r"((r)[1]),  "=r"((r)[2]),  "=r"((r)[3]), \
          "=r"((r)[4]),  "=r"((r)[5]),  "=r"((r)[6]),  "=r"((r)[7]), \
          "=r"((r)[8]),  "=r"((r)[9]),  "=r"((r)[10]), "=r"((r)[11]), \
          "=r"((r)[12]), "=r"((r)[13]), "=r"((r)[14]), "=r"((r)[15]), \
          "=r"((r)[16]), "=r"((r)[17]), "=r"((r)[18]), "=r"((r)[19]), \
          "=r"((r)[20]), "=r"((r)[21]), "=r"((r)[22]), "=r"((r)[23]), \
          "=r"((r)[24]), "=r"((r)[25]), "=r"((r)[26]), "=r"((r)[27]), \
          "=r"((r)[28]), "=r"((r)[29]), "=r"((r)[30]), "=r"((r)[31]) \
        : "r"(ta))
static constexpr uint64_t SMEM_DESC_BASE_SW128 =
    (uint64_t(2)  << 61) | (uint64_t(1) << 46) | (uint64_t(64) << 32) | (uint64_t(1) << 16);
#define MAKE_SMEM_DESC(ba) (SMEM_DESC_BASE_SW128 | ((uint64_t)((ba) >> 4) & 0x3FFF))
__device__ __forceinline__ void mma_bf16_ss(uint32_t d, uint64_t ad, uint64_t bd,
                                            uint32_t idesc, bool acc) {
    uint32_t en = acc ? 1u : 0u;
    asm volatile(
        "{\n\t.reg .pred p;\n\t"
        "setp.ne.u32 p, %5, 0;\n\t"
        "tcgen05.mma.cta_group::1.kind::f16 [%0], %1, %2, %3, {%4, %4, %4, %4}, p;\n\t"
        "}"
        :: "r"(d), "l"(ad), "l"(bd), "r"(idesc), "r"(0u), "r"(en)
        : "memory");
}
#endif  // __CUDA_ARCH_FEAT_SM103_ALL

// ---------------------------------------------------------------------------
// GEMM: C[M,N] = A[M,K] * B[N,K]^T, split-bf16 3-pass. Operands are BLOCKED
// (see top). tcgen05: CTA 256x256, TK=32, two M=128 TMEM accumulators,
// 3-stage pipeline; loads are 2x32KB cp.async.bulk per chunk, mainloop driven
// by ONE elected thread (no per-chunk CTA barrier); MMA wait deferred 1 chunk.
// MODE 1: blocked out (+bias)               [Q,K proj]
// MODE 2: blocked transposed out (+bias)    [V proj -> Vt rows=v, k=s]
// MODE 3: e=expf(acc*alpha) blocked out + row-sum atomics  [scores -> P]
// MODE 4: f32 out = acc / rowsum[m]         [PV]
// ---------------------------------------------------------------------------
constexpr int OFF_B  = 32768;
constexpr int STAGE  = 65536;                     // 32KB A + 32KB B
constexpr int SMEM_DATA = 1024;
constexpr int SMEM_TOTAL = SMEM_DATA + 3 * STAGE; // 197632

template <int MODE>
__global__ void __launch_bounds__(256, 1) tc_gemm(
    const uint8_t* __restrict__ Ab, const uint8_t* __restrict__ Bb,
    const float* __restrict__ bias,
    float* __restrict__ Cf, uint8_t* __restrict__ Cb,
    float* __restrict__ rs,
    int K, float alpha,
    size_t sAb, size_t sBb, size_t sC)
{
    extern __shared__ char smem[];
    const int tid   = threadIdx.x;
    const size_t zb = blockIdx.z;
    const int m0    = blockIdx.y * 256;
    const int n0    = blockIdx.x * 256;
    const int NC    = K >> 5;                 // k-chunks; also blocks-per-row-tile
    Ab += zb * sAb;  Bb += zb * sBb;
    const size_t blkA0 = ((size_t)(m0 >> 8)) * NC;   // block row base (A)
    const size_t blkB0 = ((size_t)(n0 >> 8)) * NC;

#if defined(__CUDA_ARCH_FEAT_SM103_ALL)
    // ======================= tcgen05 path (sm_103a) ========================
    const uint32_t sb = smem_u32(smem);

    if (tid < 32) TCGEN05_ALLOC(sb + 0, 512);
    if (tid >= 32 && tid < 64) TCGEN05_RELINQUISH();
    if (tid == 0) {
#pragma unroll
        for (int s = 0; s < 3; ++s) {
            MBAR_INIT(sb + 8  + 8 * s, 1);   // full (tx-based)
            MBAR_INIT(sb + 32 + 8 * s, 1);   // mma done
        }
    }
    __syncthreads();
    uint32_t tmem;
    asm volatile("ld.shared.b32 %0, [%1];" : "=r"(tmem) : "r"(sb + 0));

    constexpr uint32_t IDESC =
        (1u << 4) | (1u << 7) | (1u << 10) | ((256 / 8) << 17) | ((128 / 16) << 24);

    if (tid < 32 && elect_one_pred()) {
        auto load_chunk = [&](int kc, int st) {
            const uint32_t full = sb + 8 + 8 * st;
            const uint32_t base = sb + SMEM_DATA + st * STAGE;
            MBAR_EXPECT(full, STAGE);
            bulk_ld(base,         Ab + ((blkA0 + kc) << 15), 32768, full);
            bulk_ld(base + OFF_B, Bb + ((blkB0 + kc) << 15), 32768, full);
        };

        load_chunk(0, 0);
        load_chunk(1, 1);
        load_chunk(2, 2);

        int fph[3] = {0, 0, 0}, mph[3] = {0, 0, 0};
        for (int c = 0; c < NC; ++c) {
            const int st = c % 3;
            MBAR_WAIT(sb + 8 + 8 * st, fph[st]);
            fph[st] ^= 1;

            const uint32_t base = sb + SMEM_DATA + st * STAGE;
            const uint64_t daA0 = MAKE_SMEM_DESC(base);
            const uint64_t daA1 = MAKE_SMEM_DESC(base + 16384);
            const uint64_t db   = MAKE_SMEM_DESC(base + OFF_B);
#pragma unroll
            for (int half = 0; half < 2; ++half) {
                const uint64_t da = half ? daA1 : daA0;
                const uint32_t dt = tmem + half * 256;
                mma_bf16_ss(dt, da + 0, db + 0, IDESC, c != 0);   // hi*hi ks0
                mma_bf16_ss(dt, da + 2, db + 2, IDESC, true);     // hi*hi ks1
                mma_bf16_ss(dt, da + 0, db + 4, IDESC, true);     // hi*lo ks0
                mma_bf16_ss(dt, da + 2, db + 6, IDESC, true);     // hi*lo ks1
                mma_bf16_ss(dt, da + 4, db + 0, IDESC, true);     // lo*hi ks0
                mma_bf16_ss(dt, da + 6, db + 2, IDESC, true);     // lo*hi ks1
            }
            TCGEN05_COMMIT(sb + 32 + 8 * st);

            if (c > 0) {
                const int sp = (c - 1) % 3;            // == (c+2)%3
                MBAR_WAIT(sb + 32 + 8 * sp, mph[sp]);
                mph[sp] ^= 1;
                if (c + 2 < NC) load_chunk(c + 2, sp);
            }
        }
        MBAR_WAIT(sb + 32 + 8 * ((NC - 1) % 3), mph[(NC - 1) % 3]);
    }
    __syncthreads();
    TCGEN05_FENCE_AFTER();

    // epilogue: warps 0-3 -> D0 (rows 0-127), warps 4-7 -> D1 (rows 128-255)
    {
        const int half = tid >> 7;
        const int w4   = (tid >> 5) & 3;
        const int lid  = tid & 31;
        const int m    = m0 + half * 128 + w4 * 32 + lid;
        const uint32_t dt = tmem + half * 256;
        float inv = 1.0f, lsum = 0.0f;
        if (MODE == 4) inv = 1.0f / rs[zb * SEQ + m];
        for (int j0 = 0; j0 < 256; j0 += 32) {
            uint32_t r[32];
            TCGEN05_LD_32X32B_X32(r, dt + j0);
            TCGEN05_WAIT_LD();
            if (MODE == 4) {
                float4* dst = (float4*)(Cf + zb * sC + (size_t)m * DM + n0 + j0);
#pragma unroll
                for (int i = 0; i < 8; ++i) {
                    float4 v;
                    v.x = __uint_as_float(r[4 * i + 0]) * inv;
                    v.y = __uint_as_float(r[4 * i + 1]) * inv;
                    v.z = __uint_as_float(r[4 * i + 2]) * inv;
                    v.w = __uint_as_float(r[4 * i + 3]) * inv;
                    dst[i] = v;
                }
            } else if (MODE == 1 || MODE == 3) {
                uint32_t H[16], L[16];
#pragma unroll
                for (int i = 0; i < 32; i += 2) {
                    float v0, v1;
                    if (MODE == 3) {
                        v0 = __expf(__uint_as_float(r[i])     * alpha);
                        v1 = __expf(__uint_as_float(r[i + 1]) * alpha);
                        lsum += v0 + v1;
                    } else {
                        v0 = __uint_as_float(r[i])     + bias[n0 + j0 + i];
                        v1 = __uint_as_float(r[i + 1]) + bias[n0 + j0 + i + 1];
                    }
                    __nv_bfloat16 h0, l0, h1, l1;
                    split2(v0, h0, l0); split2(v1, h1, l1);
                    H[i >> 1] = pkbf2(h0, h1);
                    L[i >> 1] = pkbf2(l0, l1);
                }
                uint8_t* base;
                size_t blk;
                int row;
                if (MODE == 1) {      // per-batch blocks, nkc = DM/32 = 32
                    base = Cb + (size_t)(m >> 11) * 8388608u;
                    blk  = ((((size_t)((m & 2047) >> 8)) * 32) + ((n0 + j0) >> 5)) << 15;
                    row  = m & 255;
                } else {              // P: nkc = SEQ/32 = 64, batch stride 16MB
                    base = Cb + zb * 16777216u;
                    blk  = ((((size_t)(m >> 8)) * 64) + ((n0 + j0) >> 5)) << 15;
                    row  = m & 255;
                }
#pragma unroll
                for (int q = 0; q < 4; ++q) {
                    uint4 hv; hv.x = H[4*q]; hv.y = H[4*q+1]; hv.z = H[4*q+2]; hv.w = H[4*q+3];
                    uint4 lv; lv.x = L[4*q]; lv.y = L[4*q+1]; lv.z = L[4*q+2]; lv.w = L[4*q+3];
                    *(uint4*)(base + blk + SWZ128((uint32_t)row * 128 + q * 16))      = hv;
                    *(uint4*)(base + blk + SWZ128((uint32_t)row * 128 + 64 + q * 16)) = lv;
                }
            } else {  // MODE 2: Vt scatter (rows = v = n, k = s = m within batch)
                uint8_t* base = Cb + (size_t)(m >> 11) * 8388608u;
                const int sx = m & 2047;
#pragma unroll
                for (int i = 0; i < 32; ++i) {
                    const int n = n0 + j0 + i;
                    store_blk2(base, n, sx, 64, __uint_as_float(r[i]) + bias[n]);
                }
            }
        }
        if (MODE == 3) atomicAdd(&rs[zb * SEQ + m], lsum);
    }
    __syncthreads();
    if (tid < 32) TCGEN05_DEALLOC(tmem, 512);

#elif defined(__CUDA_ARCH__)
    // ================= mma.sync fallback (base compute_103) =================
    // Correctness insurance only (sm_103a cubin is the one that runs).
    constexpr int STR = 20;
    constexpr int TILE_W = 128 * STR;
    constexpr int STAGE_W = 4 * TILE_W;
    const uint32_t sbase = smem_u32(smem);
    const int lane = tid & 31, wid = tid >> 5;
    const int wm = wid >> 1, wn = wid & 1;
    const int g = lane >> 2, tg = lane & 3;

    auto load_chunk = [&](int kc, int st, int mbase, int nbase) {
        const int q = tid & 3, r0 = tid >> 2;
        const uint32_t dst0 = sbase + st * STAGE_W * 4;
#pragma unroll
        for (int i = 0; i < 2; ++i) {
            const int ra = mbase + r0 + 64 * i;
            const int rb = nbase + r0 + 64 * i;
            const uint32_t ro = (uint32_t)((r0 + 64 * i) * STR + q * 4) * 4;
            const size_t ba = ((blkA0 + kc) + ((size_t)(ra >> 8) - (m0 >> 8)) * NC) << 15;
            const size_t bb = ((blkB0 + kc) + ((size_t)(rb >> 8) - (n0 >> 8)) * NC) << 15;
            const uint32_t oa = (uint32_t)(ra & 255) * 128 + q * 16;
            const uint32_t ob = (uint32_t)(rb & 255) * 128 + q * 16;
            cp16(dst0 + 0 * TILE_W * 4 + ro, Ab + ba + SWZ128(oa));
            cp16(dst0 + 1 * TILE_W * 4 + ro, Ab + ba + SWZ128(oa + 64));
            cp16(dst0 + 2 * TILE_W * 4 + ro, Bb + bb + SWZ128(ob));
            cp16(dst0 + 3 * TILE_W * 4 + ro, Bb + bb + SWZ128(ob + 64));
        }
    };

    for (int mh = 0; mh < 2; ++mh) {
        const int mb0 = m0 + mh * 128;
        for (int np = 0; np < 2; ++np) {
            const int nb0 = n0 + np * 128;

            float acc[2][8][4];
#pragma unroll
            for (int a = 0; a < 2; ++a)
#pragma unroll
                for (int b = 0; b < 8; ++b)
#pragma unroll
                    for (int c = 0; c < 4; ++c) acc[a][b][c] = 0.0f;

            load_chunk(0, 0, mb0, nb0); CP_COMMIT();

            for (int c = 0; c < NC; ++c) {
                const int st = c & 1;
                if (c + 1 < NC) { load_chunk(c + 1, st ^ 1, mb0, nb0); CP_COMMIT(); CP_WAIT(1); }
                else            { CP_WAIT(0); }
                __syncthreads();

                const uint32_t* s0 = (const uint32_t*)smem + st * STAGE_W;
#pragma unroll
                for (int ks = 0; ks < 2; ++ks) {
                    uint32_t ahf[2][4], alf[2][4];
#pragma unroll
                    for (int mt = 0; mt < 2; ++mt) {
                        const int rb = wm * 32 + mt * 16;
                        const uint32_t* pa = s0 + (rb + g) * STR + ks * 8 + tg;
                        ahf[mt][0] = pa[0];           ahf[mt][2] = pa[4];
                        ahf[mt][1] = pa[8 * STR];     ahf[mt][3] = pa[8 * STR + 4];
                        const uint32_t* pl = pa + TILE_W;
                        alf[mt][0] = pl[0];           alf[mt][2] = pl[4];
                        alf[mt][1] = pl[8 * STR];     alf[mt][3] = pl[8 * STR + 4];
                    }
#pragma unroll
                    for (int nt = 0; nt < 8; ++nt) {
                        const int nb = wn * 64 + nt * 8;
                        const uint32_t* pb = s0 + 2 * TILE_W + (nb + g) * STR + ks * 8 + tg;
                        const uint32_t bh0 = pb[0], bh1 = pb[4];
                        const uint32_t* pbl = pb + TILE_W;
                        const uint32_t bl0 = pbl[0], bl1 = pbl[4];
#pragma unroll
                        for (int mt = 0; mt < 2; ++mt) {
                            mma16816(acc[mt][nt], ahf[mt], bh0, bh1);
                            mma16816(acc[mt][nt], ahf[mt], bl0, bl1);
                            mma16816(acc[mt][nt], alf[mt], bh0, bh1);
                        }
                    }
                }
                __syncthreads();
            }

#pragma unroll
            for (int mt = 0; mt < 2; ++mt) {
#pragma unroll
                for (int nt = 0; nt < 8; ++nt) {
                    const int m1 = mb0 + wm * 32 + mt * 16 + g;
                    const int m2 = m1 + 8;
                    const int n  = nb0 + wn * 64 + nt * 8 + tg * 2;
                    const float* a = acc[mt][nt];
                    if (MODE == 4) {
                        const float i1 = 1.0f / rs[zb * SEQ + m1];
                        const float i2 = 1.0f / rs[zb * SEQ + m2];
                        float2 v0; v0.x = a[0] * i1; v0.y = a[1] * i1;
                        float2 v1; v1.x = a[2] * i2; v1.y = a[3] * i2;
                        *(float2*)(Cf + zb * sC + (size_t)m1 * DM + n) = v0;
                        *(float2*)(Cf + zb * sC + (size_t)m2 * DM + n) = v1;
                    } else if (MODE == 1) {
#pragma unroll
                        for (int e = 0; e < 4; ++e) {
                            const int m = (e < 2) ? m1 : m2;
                            const int nn = n + (e & 1);
                            store_blk2(Cb + (size_t)(m >> 11) * 8388608u,
                                       m & 2047, nn, 32, a[e] + bias[nn]);
                        }
                    } else if (MODE == 3) {
                        float e0 = __expf(a[0] * alpha), e1 = __expf(a[1] * alpha);
                        float e2 = __expf(a[2] * alpha), e3 = __expf(a[3] * alpha);
                        atomicAdd(&rs[zb * SEQ + m1], e0 + e1);
                        atomicAdd(&rs[zb * SEQ + m2], e2 + e3);
                        uint8_t* base = Cb + zb * 16777216u;
                        store_blk2(base, m1, n,     64, e0);
                        store_blk2(base, m1, n + 1, 64, e1);
                        store_blk2(base, m2, n,     64, e2);
                        store_blk2(base, m2, n + 1, 64, e3);
                    } else {  // MODE 2
#pragma unroll
                        for (int e = 0; e < 4; ++e) {
                            const int m = (e < 2) ? m1 : m2;
                            const int nn = n + (e & 1);
                            store_blk2(Cb + (size_t)(m >> 11) * 8388608u,
                                       nn, m & 2047, 64, a[e] + bias[nn]);
                        }
                    }
                }
            }
            __syncthreads();
        }
    }
#endif
}

// ---------------------------------------------------------------------------
// f32 -> blocked split-bf16 (K fixed = 1024 for inputs and weights)
// one 16B unit (8 elems) per thread-iteration
// ---------------------------------------------------------------------------
__global__ void __launch_bounds__(256) split_k(
    const float* __restrict__ x, uint8_t* __restrict__ dst, int nunits)
{
    for (int u = blockIdx.x * 256 + threadIdx.x; u < nunits; u += gridDim.x * 256) {
        const int r  = u >> 7;        // row (K=1024 -> 128 units/row)
        const int ku = u & 127;
        const int kc = ku >> 2;
        const int q  = ku & 3;
        const float4 f0 = *(const float4*)(x + ((size_t)r << 10) + (ku << 3));
        const float4 f1 = *(const float4*)(x + ((size_t)r << 10) + (ku << 3) + 4);
        const float v[8] = {f0.x, f0.y, f0.z, f0.w, f1.x, f1.y, f1.z, f1.w};
        __nv_bfloat16 h[8], l[8];
#pragma unroll
        for (int i = 0; i < 8; ++i) split2(v[i], h[i], l[i]);
        uint4 hv, lv;
        hv.x = pkbf2(h[0], h[1]); hv.y = pkbf2(h[2], h[3]);
        hv.z = pkbf2(h[4], h[5]); hv.w = pkbf2(h[6], h[7]);
        lv.x = pkbf2(l[0], l[1]); lv.y = pkbf2(l[2], l[3]);
        lv.z = pkbf2(l[4], l[5]); lv.w = pkbf2(l[6], l[7]);
        const size_t blk = ((((size_t)(r >> 8)) << 5) + kc) << 15;  // nkc = 32
        const uint32_t ro = (uint32_t)(r & 255) * 128 + q * 16;
        *(uint4*)(dst + blk + SWZ128(ro))      = hv;
        *(uint4*)(dst + blk + SWZ128(ro + 64)) = lv;
    }
}

__global__ void __launch_bounds__(1024) zero_k(float* __restrict__ p, int n)
{
    int i = blockIdx.x * 1024 + threadIdx.x;
    if (i < n) p[i] = 0.0f;
}

// ---------------------------------------------------------------------------
extern "C" void kernel_launch(void* const* d_in, const int* in_sizes, int n_in,
                              void* d_out, int out_size)
{
    (void)in_sizes; (void)n_in; (void)out_size;
    const float* q  = (const float*)d_in[0];
    const float* kx = (const float*)d_in[1];
    const float* vx = (const float*)d_in[2];
    const float* Wq = (const float*)d_in[3];
    const float* bq = (const float*)d_in[4];
    const float* Wk = (const float*)d_in[5];
    const float* bk = (const float*)d_in[6];
    const float* Wv = (const float*)d_in[7];
    const float* bv = (const float*)d_in[8];
    float* out = (float*)d_out;

    uint8_t *Xq, *Xk, *Xv, *Wqb, *Wkb, *Wvb, *Qb, *Kb, *Vt, *Pb;
    float* rs;
    cudaGetSymbolAddress((void**)&Xq,  g_Xq);  cudaGetSymbolAddress((void**)&Xk,  g_Xk);
    cudaGetSymbolAddress((void**)&Xv,  g_Xv);
    cudaGetSymbolAddress((void**)&Wqb, g_Wq);  cudaGetSymbolAddress((void**)&Wkb, g_Wk);
    cudaGetSymbolAddress((void**)&Wvb, g_Wv);
    cudaGetSymbolAddress((void**)&Qb,  g_Qb);  cudaGetSymbolAddress((void**)&Kb,  g_Kb);
    cudaGetSymbolAddress((void**)&Vt,  g_Vt);  cudaGetSymbolAddress((void**)&Pb,  g_Pb);
    cudaGetSymbolAddress((void**)&rs,  g_rs);

    cudaFuncSetAttribute(tc_gemm<1>, cudaFuncAttributeMaxDynamicSharedMemorySize, SMEM_TOTAL);
    cudaFuncSetAttribute(tc_gemm<2>, cudaFuncAttributeMaxDynamicSharedMemorySize, SMEM_TOTAL);
    cudaFuncSetAttribute(tc_gemm<3>, cudaFuncAttributeMaxDynamicSharedMemorySize, SMEM_TOTAL);
    cudaFuncSetAttribute(tc_gemm<4>, cudaFuncAttributeMaxDynamicSharedMemorySize, SMEM_TOTAL);

    // 1. split inputs & weights into blocked bf16 hi/lo; zero row sums
    split_k<<<4096, 256>>>(q,  Xq,  NTOK * DIN / 8);
    split_k<<<4096, 256>>>(kx, Xk,  NTOK * DIN / 8);
    split_k<<<4096, 256>>>(vx, Xv,  NTOK * DIN / 8);
    split_k<<<512,  256>>>(Wq, Wqb, DM * DIN / 8);
    split_k<<<512,  256>>>(Wk, Wkb, DM * DIN / 8);
    split_k<<<512,  256>>>(Wv, Wvb, DM * DIN / 8);
    zero_k<<<(BN * SEQ + 1023) / 1024, 1024>>>(rs, BN * SEQ);

    // 2. projections
    dim3 gP(DM / 256, NTOK / 256, 1);
    tc_gemm<1><<<gP, 256, SMEM_TOTAL>>>(Xq, Wqb, bq, nullptr, Qb, nullptr,
                                        DIN, 1.0f, 0, 0, 0);
    tc_gemm<1><<<gP, 256, SMEM_TOTAL>>>(Xk, Wkb, bk, nullptr, Kb, nullptr,
                                        DIN, 1.0f, 0, 0, 0);
    tc_gemm<2><<<gP, 256, SMEM_TOTAL>>>(Xv, Wvb, bv, nullptr, Vt, nullptr,
                                        DIN, 1.0f, 0, 0, 0);

    // 3. scores + exp + row sums -> blocked P
    dim3 gS(SEQ / 256, SEQ / 256, BN);
    tc_gemm<3><<<gS, 256, SMEM_TOTAL>>>(Qb, Kb, nullptr, nullptr, Pb, rs,
                                        DM, 0.03125f, 8388608u, 8388608u, 0);

    // 4. O = (P * Vt^T) / rowsum
    dim3 gO(DM / 256, SEQ / 256, BN);
    tc_gemm<4><<<gO, 256, SMEM_TOTAL>>>(Pb, Vt, nullptr, out, nullptr, rs,
                                        SEQ, 1.0f, 16777216u, 8388608u,
                                        (size_t)SEQ * DM);
}

// round 8
// speedup vs baseline: 1.7915x; 1.0034x over previous
#include <cuda_runtime.h>
#include <cuda_bf16.h>
#include <cstdint>

// ---------------------------------------------------------------------------
// Problem constants
// ---------------------------------------------------------------------------
#define BN   8
#define SEQ  2048
#define DIN  1024
#define DM   1024
#define NTOK (BN*SEQ)          // 16384

// ---------------------------------------------------------------------------
// Blocked-operand layout (round-7 validated):
//   operand[row, k] stored as 32KB blocks indexed [row/256][k/32].
//   Block: 256 rows x 128B; row image = [hi k0..31 (64B) | lo k0..31],
//   SW128-swizzled. GEMM chunk load = TWO contiguous 32KB cp.async.bulk.
// ---------------------------------------------------------------------------
#define SWZ128(off) ((off) ^ (((off) >> 3) & 0x70))

__device__ uint8_t g_Xq[(size_t)NTOK*DIN*4];
__device__ uint8_t g_Xk[(size_t)NTOK*DIN*4];
__device__ uint8_t g_Xv[(size_t)NTOK*DIN*4];
__device__ uint8_t g_Wq[(size_t)DM*DIN*4];
__device__ uint8_t g_Wk[(size_t)DM*DIN*4];
__device__ uint8_t g_Wv[(size_t)DM*DIN*4];
__device__ uint8_t g_Qb[(size_t)NTOK*DM*4];          // token rows, nkc=32
__device__ uint8_t g_Kb[(size_t)NTOK*DM*4];
__device__ uint8_t g_Vt[(size_t)BN*DM*SEQ*4];        // rows=v, k=s, nkc=64, 8MB/batch
__device__ uint8_t g_Pb[(size_t)BN*SEQ*SEQ*4];       // rows=q, k=s, nkc=64, 16MB/batch
__device__ float   g_rs[(size_t)BN*SEQ];

// ---------------------------------------------------------------------------
// Helpers available on base compute_103
// ---------------------------------------------------------------------------
__device__ __forceinline__ uint32_t smem_u32(const void* p) {
    uint32_t a;
    asm("{ .reg .u64 t; cvta.to.shared.u64 t, %1; cvt.u32.u64 %0, t; }"
        : "=r"(a) : "l"(p));
    return a;
}
__device__ __forceinline__ void cp16(uint32_t dst, const void* src) {
    asm volatile("cp.async.cg.shared.global [%0], [%1], 16;" :: "r"(dst), "l"(src));
}
#define CP_COMMIT()  asm volatile("cp.async.commit_group;" ::: "memory")
#define CP_WAIT(N)   asm volatile("cp.async.wait_group %0;" :: "n"(N) : "memory")

__device__ __forceinline__ void mma16816(float* c, const uint32_t* a,
                                         uint32_t b0, uint32_t b1) {
    asm volatile(
        "mma.sync.aligned.m16n8k16.row.col.f32.bf16.bf16.f32 "
        "{%0,%1,%2,%3}, {%4,%5,%6,%7}, {%8,%9}, {%0,%1,%2,%3};"
        : "+f"(c[0]), "+f"(c[1]), "+f"(c[2]), "+f"(c[3])
        : "r"(a[0]), "r"(a[1]), "r"(a[2]), "r"(a[3]), "r"(b0), "r"(b1));
}

__device__ __forceinline__ void split2(float v, __nv_bfloat16& h, __nv_bfloat16& l) {
    h = __float2bfloat16(v);
    l = __float2bfloat16(v - __bfloat162float(h));
}
__device__ __forceinline__ uint32_t pkbf2(__nv_bfloat16 a, __nv_bfloat16 b) {
    __nv_bfloat162 t; t.x = a; t.y = b;
    return *(uint32_t*)&t;
}
__device__ __forceinline__ void store_blk2(uint8_t* base, int row, int k,
                                           int nkc, float v) {
    const size_t blk = (((size_t)(row >> 8)) * nkc + (k >> 5)) << 15;
    const uint32_t off = (uint32_t)(row & 255) * 128 + ((k & 31) >> 3) * 16 + (k & 7) * 2;
    __nv_bfloat16 h, l;
    split2(v, h, l);
    *(__nv_bfloat16*)(base + blk + SWZ128(off))      = h;
    *(__nv_bfloat16*)(base + blk + SWZ128(off + 64)) = l;
}

// bulk copy (UBLKCP): contiguous gmem -> smem, completion via mbarrier tx-bytes
__device__ __forceinline__ void bulk_ld(uint32_t dst, const void* src,
                                        uint32_t bytes, uint32_t mbar) {
    asm volatile(
        "cp.async.bulk.shared::cluster.global.mbarrier::complete_tx::bytes "
        "[%0], [%1], %2, [%3];"
        :: "r"(dst), "l"(src), "r"(bytes), "r"(mbar) : "memory");
}
#define MBAR_INIT(addr, cnt) \
    asm volatile("mbarrier.init.shared.b64 [%0], %1;" :: "r"((uint32_t)(addr)), "r"((uint32_t)(cnt)) : "memory")
#define MBAR_EXPECT(addr, tx) \
    asm volatile("mbarrier.arrive.expect_tx.shared.b64 _, [%0], %1;" :: "r"((uint32_t)(addr)), "r"((uint32_t)(tx)) : "memory")
#define MBAR_WAIT(mbar, par) do { \
    uint32_t _m = (uint32_t)(mbar), _p = (uint32_t)(par), _d; \
    asm volatile("{\n\t.reg .pred p;\n\t" \
        "mbarrier.try_wait.parity.acquire.cta.shared::cta.b64 p, [%1], %2;\n\t" \
        "selp.b32 %0, 1, 0, p;\n\t}" : "=r"(_d) : "r"(_m), "r"(_p) : "memory"); \
    if (!_d) { \
        asm volatile("{\n\t.reg .pred P1;\n\t" \
            "WL_%=:\n\t" \
            "mbarrier.try_wait.parity.acquire.cta.shared::cta.b64 P1, [%0], %1, 0x989680;\n\t" \
            "@P1 bra.uni WD_%=;\n\tbra.uni WL_%=;\n\tWD_%=:\n\t}" \
            :: "r"(_m), "r"(_p) : "memory"); \
    } \
} while (0)

// ---------------------------------------------------------------------------
// tcgen05 helpers — ONLY compiled when the build has a compute_103a pass.
// ---------------------------------------------------------------------------
#if defined(__CUDA_ARCH_FEAT_SM103_ALL)
__device__ __forceinline__ uint32_t elect_one_pred() {
    uint32_t pred;
    asm volatile(
        "{\n\t.reg .pred p;\n\t"
        "elect.sync _|p, 0xFFFFFFFF;\n\t"
        "selp.b32 %0, 1, 0, p;\n\t}"
        : "=r"(pred));
    return pred;
}
#define TCGEN05_ALLOC(a, n) \
    asm volatile("tcgen05.alloc.cta_group::1.sync.aligned.shared::cta.b32 [%0], %1;" \
        :: "r"((uint32_t)(a)), "r"((uint32_t)(n)) : "memory")
#define TCGEN05_RELINQUISH() \
    asm volatile("tcgen05.relinquish_alloc_permit.cta_group::1.sync.aligned;")
#define TCGEN05_DEALLOC(t, n) \
    asm volatile("tcgen05.dealloc.cta_group::1.sync.aligned.b32 %0, %1;" :: "r"(t), "r"((uint32_t)(n)))
#define TCGEN05_COMMIT(m) \
    asm volatile("tcgen05.commit.cta_group::1.mbarrier::arrive::one.shared::cluster.b64 [%0];" \
        :: "r"((uint32_t)(m)) : "memory")
#define TCGEN05_WAIT_LD()    asm volatile("tcgen05.wait::ld.sync.aligned;" ::: "memory")
#define TCGEN05_FENCE_AFTER() asm volatile("tcgen05.fence::after_thread_sync;" ::: "memory")
#define TCGEN05_LD_32X32B_X32(r, ta) \
    asm volatile( \
        "tcgen05.ld.sync.aligned.32x32b.x32.b32 " \
        "{%0, %1, %2, %3, %4, %5, %6, %7, " \
        " %8, %9, %10, %11, %12, %13, %14, %15, " \
        " %16, %17, %18, %19, %20, %21, %22, %23, " \
        " %24, %25, %26, %27, %28, %29, %30, %31}, [%32];" \
        : "=r"((r)[0]),  "=r"((r)[1]),  "=r"((r)[2]),  "=r"((r)[3]), \
          "=r"((r)[4]),  "=r"((r)[5]),  "=r"((r)[6]),  "=r"((r)[7]), \
          "=r"((r)[8]),  "=r"((r)[9]),  "=r"((r)[10]), "=r"((r)[11]), \
          "=r"((r)[12]), "=r"((r)[13]), "=r"((r)[14]), "=r"((r)[15]), \
          "=r"((r)[16]), "=r"((r)[17]), "=r"((r)[18]), "=r"((r)[19]), \
          "=r"((r)[20]), "=r"((r)[21]), "=r"((r)[22]), "=r"((r)[23]), \
          "=r"((r)[24]), "=r"((r)[25]), "=r"((r)[26]), "=r"((r)[27]), \
          "=r"((r)[28]), "=r"((r)[29]), "=r"((r)[30]), "=r"((r)[31]) \
        : "r"(ta))
static constexpr uint64_t SMEM_DESC_BASE_SW128 =
    (uint64_t(2)  << 61) | (uint64_t(1) << 46) | (uint64_t(64) << 32) | (uint64_t(1) << 16);
#define MAKE_SMEM_DESC(ba) (SMEM_DESC_BASE_SW128 | ((uint64_t)((ba) >> 4) & 0x3FFF))
__device__ __forceinline__ void mma_bf16_ss(uint32_t d, uint64_t ad, uint64_t bd,
                                            uint32_t idesc, bool acc) {
    uint32_t en = acc ? 1u : 0u;
    asm volatile(
        "{\n\t.reg .pred p;\n\t"
        "setp.ne.u32 p, %5, 0;\n\t"
        "tcgen05.mma.cta_group::1.kind::f16 [%0], %1, %2, %3, {%4, %4, %4, %4}, p;\n\t"
        "}"
        :: "r"(d), "l"(ad), "l"(bd), "r"(idesc), "r"(0u), "r"(en)
        : "memory");
}
#endif  // __CUDA_ARCH_FEAT_SM103_ALL

// ---------------------------------------------------------------------------
// GEMM: C[M,N] = A[M,K] * B[N,K]^T, split-bf16 3-pass, blocked operands.
// tcgen05: CTA 256x256, TK=32, two M=128 TMEM accumulators, 3-stage pipeline,
// 2x32KB bulk loads/chunk, single-elected-thread mainloop, deferred MMA wait.
// MODE 0: dual projection (z selects {Xq,Wq,bq,Qb} / {Xk,Wk,bk,Kb}), bias[n]
// MODE 2: Vt = Wv * Xv^T (+bias[m]); A=Wv (unbatched), B=Xv (8MB/batch)
// MODE 3: e=expf(acc*alpha) blocked out + row-sum atomics  [scores -> P]
// MODE 4: f32 out = acc / rowsum[m]         [PV]
// ---------------------------------------------------------------------------
constexpr int OFF_B  = 32768;
constexpr int STAGE  = 65536;                     // 32KB A + 32KB B
constexpr int SMEM_DATA = 1024;
constexpr int SMEM_TOTAL = SMEM_DATA + 3 * STAGE; // 197632

template <int MODE>
__global__ void __launch_bounds__(256, 1) tc_gemm(
    const uint8_t* __restrict__ Ab, const uint8_t* __restrict__ Bb,
    const uint8_t* __restrict__ A2b, const uint8_t* __restrict__ B2b,
    const float* __restrict__ bias, const float* __restrict__ bias2,
    float* __restrict__ Cf, uint8_t* __restrict__ Cb, uint8_t* __restrict__ C2b,
    float* __restrict__ rs,
    int K, float alpha,
    size_t sAb, size_t sBb, size_t sC)
{
    extern __shared__ char smem[];
    const int tid   = threadIdx.x;
    const size_t zb = blockIdx.z;
    const int m0    = blockIdx.y * 256;
    const int n0    = blockIdx.x * 256;
    const int NC    = K >> 5;

    if (MODE == 0 && zb == 1) {       // z selects the K-projection operand set
        Ab = A2b; Bb = B2b; Cb = C2b; bias = bias2;
    }
    Ab += zb * sAb;  Bb += zb * sBb;
    const size_t blkA0 = ((size_t)(m0 >> 8)) * NC;
    const size_t blkB0 = ((size_t)(n0 >> 8)) * NC;

#if defined(__CUDA_ARCH_FEAT_SM103_ALL)
    // ======================= tcgen05 path (sm_103a) ========================
    const uint32_t sb = smem_u32(smem);

    if (tid < 32) TCGEN05_ALLOC(sb + 0, 512);
    if (tid >= 32 && tid < 64) TCGEN05_RELINQUISH();
    if (tid == 0) {
#pragma unroll
        for (int s = 0; s < 3; ++s) {
            MBAR_INIT(sb + 8  + 8 * s, 1);   // full (tx-based)
            MBAR_INIT(sb + 32 + 8 * s, 1);   // mma done
        }
    }
    __syncthreads();
    uint32_t tmem;
    asm volatile("ld.shared.b32 %0, [%1];" : "=r"(tmem) : "r"(sb + 0));

    constexpr uint32_t IDESC =
        (1u << 4) | (1u << 7) | (1u << 10) | ((256 / 8) << 17) | ((128 / 16) << 24);

    if (tid < 32 && elect_one_pred()) {
        auto load_chunk = [&](int kc, int st) {
            const uint32_t full = sb + 8 + 8 * st;
            const uint32_t base = sb + SMEM_DATA + st * STAGE;
            MBAR_EXPECT(full, STAGE);
            bulk_ld(base,         Ab + ((blkA0 + kc) << 15), 32768, full);
            bulk_ld(base + OFF_B, Bb + ((blkB0 + kc) << 15), 32768, full);
        };

        load_chunk(0, 0);
        load_chunk(1, 1);
        load_chunk(2, 2);

        int fph[3] = {0, 0, 0}, mph[3] = {0, 0, 0};
        for (int c = 0; c < NC; ++c) {
            const int st = c % 3;
            MBAR_WAIT(sb + 8 + 8 * st, fph[st]);
            fph[st] ^= 1;

            const uint32_t base = sb + SMEM_DATA + st * STAGE;
            const uint64_t daA0 = MAKE_SMEM_DESC(base);
            const uint64_t daA1 = MAKE_SMEM_DESC(base + 16384);
            const uint64_t db   = MAKE_SMEM_DESC(base + OFF_B);
#pragma unroll
            for (int half = 0; half < 2; ++half) {
                const uint64_t da = half ? daA1 : daA0;
                const uint32_t dt = tmem + half * 256;
                mma_bf16_ss(dt, da + 0, db + 0, IDESC, c != 0);
                mma_bf16_ss(dt, da + 2, db + 2, IDESC, true);
                mma_bf16_ss(dt, da + 0, db + 4, IDESC, true);
                mma_bf16_ss(dt, da + 2, db + 6, IDESC, true);
                mma_bf16_ss(dt, da + 4, db + 0, IDESC, true);
                mma_bf16_ss(dt, da + 6, db + 2, IDESC, true);
            }
            TCGEN05_COMMIT(sb + 32 + 8 * st);

            if (c > 0) {
                const int sp = (c - 1) % 3;
                MBAR_WAIT(sb + 32 + 8 * sp, mph[sp]);
                mph[sp] ^= 1;
                if (c + 2 < NC) load_chunk(c + 2, sp);
            }
        }
        MBAR_WAIT(sb + 32 + 8 * ((NC - 1) % 3), mph[(NC - 1) % 3]);
    }
    __syncthreads();
    TCGEN05_FENCE_AFTER();

    // epilogue: warps 0-3 -> D0 (rows 0-127), warps 4-7 -> D1 (rows 128-255)
    {
        const int half = tid >> 7;
        const int w4   = (tid >> 5) & 3;
        const int lid  = tid & 31;
        const int m    = m0 + half * 128 + w4 * 32 + lid;
        const uint32_t dt = tmem + half * 256;
        float inv = 1.0f, lsum = 0.0f, bm = 0.0f;
        if (MODE == 4) inv = 1.0f / rs[zb * SEQ + m];
        if (MODE == 2) bm  = bias[m];
        for (int j0 = 0; j0 < 256; j0 += 32) {
            uint32_t r[32];
            TCGEN05_LD_32X32B_X32(r, dt + j0);
            TCGEN05_WAIT_LD();
            if (MODE == 4) {
                float4* dst = (float4*)(Cf + zb * sC + (size_t)m * DM + n0 + j0);
#pragma unroll
                for (int i = 0; i < 8; ++i) {
                    float4 v;
                    v.x = __uint_as_float(r[4 * i + 0]) * inv;
                    v.y = __uint_as_float(r[4 * i + 1]) * inv;
                    v.z = __uint_as_float(r[4 * i + 2]) * inv;
                    v.w = __uint_as_float(r[4 * i + 3]) * inv;
                    dst[i] = v;
                }
            } else {   // MODE 0 / 2 / 3: blocked vectorized hi/lo store
                uint32_t H[16], L[16];
#pragma unroll
                for (int i = 0; i < 32; i += 2) {
                    float v0, v1;
                    if (MODE == 3) {
                        v0 = __expf(__uint_as_float(r[i])     * alpha);
                        v1 = __expf(__uint_as_float(r[i + 1]) * alpha);
                        lsum += v0 + v1;
                    } else if (MODE == 0) {
                        v0 = __uint_as_float(r[i])     + bias[n0 + j0 + i];
                        v1 = __uint_as_float(r[i + 1]) + bias[n0 + j0 + i + 1];
                    } else {                      // MODE 2: per-row bias
                        v0 = __uint_as_float(r[i])     + bm;
                        v1 = __uint_as_float(r[i + 1]) + bm;
                    }
                    __nv_bfloat16 h0, l0, h1, l1;
                    split2(v0, h0, l0); split2(v1, h1, l1);
                    H[i >> 1] = pkbf2(h0, h1);
                    L[i >> 1] = pkbf2(l0, l1);
                }
                uint8_t* base;
                size_t blk;
                const int row = m & 255;
                if (MODE == 0) {          // token rows, nkc = 32, batch by m
                    base = Cb + (size_t)(m >> 11) * 8388608u;
                    blk  = ((((size_t)((m & 2047) >> 8)) * 32) + ((n0 + j0) >> 5)) << 15;
                } else if (MODE == 3) {   // P: nkc = 64, 16MB/batch
                    base = Cb + zb * 16777216u;
                    blk  = ((((size_t)(m >> 8)) * 64) + ((n0 + j0) >> 5)) << 15;
                } else {                  // MODE 2: Vt rows=v, nkc = 64, 8MB/batch
                    base = Cb + zb * 8388608u;
                    blk  = ((((size_t)(m >> 8)) * 64) + ((n0 + j0) >> 5)) << 15;
                }
#pragma unroll
                for (int q = 0; q < 4; ++q) {
                    uint4 hv; hv.x = H[4*q]; hv.y = H[4*q+1]; hv.z = H[4*q+2]; hv.w = H[4*q+3];
                    uint4 lv; lv.x = L[4*q]; lv.y = L[4*q+1]; lv.z = L[4*q+2]; lv.w = L[4*q+3];
                    *(uint4*)(base + blk + SWZ128((uint32_t)row * 128 + q * 16))      = hv;
                    *(uint4*)(base + blk + SWZ128((uint32_t)row * 128 + 64 + q * 16)) = lv;
                }
            }
        }
        if (MODE == 3) atomicAdd(&rs[zb * SEQ + m], lsum);
    }
    __syncthreads();
    if (tid < 32) TCGEN05_DEALLOC(tmem, 512);

#elif defined(__CUDA_ARCH__)
    // ================= mma.sync fallback (base compute_103) =================
    // Correctness insurance only (sm_103a cubin is the one that runs).
    constexpr int STR = 20;
    constexpr int TILE_W = 128 * STR;
    constexpr int STAGE_W = 4 * TILE_W;
    const uint32_t sbase = smem_u32(smem);
    const int lane = tid & 31, wid = tid >> 5;
    const int wm = wid >> 1, wn = wid & 1;
    const int g = lane >> 2, tg = lane & 3;

    auto load_chunk = [&](int kc, int st, int mbase, int nbase) {
        const int q = tid & 3, r0 = tid >> 2;
        const uint32_t dst0 = sbase + st * STAGE_W * 4;
#pragma unroll
        for (int i = 0; i < 2; ++i) {
            const int ra = mbase + r0 + 64 * i;
            const int rb = nbase + r0 + 64 * i;
            const uint32_t ro = (uint32_t)((r0 + 64 * i) * STR + q * 4) * 4;
            const size_t ba = ((blkA0 + kc) + ((size_t)(ra >> 8) - (m0 >> 8)) * NC) << 15;
            const size_t bb = ((blkB0 + kc) + ((size_t)(rb >> 8) - (n0 >> 8)) * NC) << 15;
            const uint32_t oa = (uint32_t)(ra & 255) * 128 + q * 16;
            const uint32_t ob = (uint32_t)(rb & 255) * 128 + q * 16;
            cp16(dst0 + 0 * TILE_W * 4 + ro, Ab + ba + SWZ128(oa));
            cp16(dst0 + 1 * TILE_W * 4 + ro, Ab + ba + SWZ128(oa + 64));
            cp16(dst0 + 2 * TILE_W * 4 + ro, Bb + bb + SWZ128(ob));
            cp16(dst0 + 3 * TILE_W * 4 + ro, Bb + bb + SWZ128(ob + 64));
        }
    };

    for (int mh = 0; mh < 2; ++mh) {
        const int mb0 = m0 + mh * 128;
        for (int np = 0; np < 2; ++np) {
            const int nb0 = n0 + np * 128;

            float acc[2][8][4];
#pragma unroll
            for (int a = 0; a < 2; ++a)
#pragma unroll
                for (int b = 0; b < 8; ++b)
#pragma unroll
                    for (int c = 0; c < 4; ++c) acc[a][b][c] = 0.0f;

            load_chunk(0, 0, mb0, nb0); CP_COMMIT();

            for (int c = 0; c < NC; ++c) {
                const int st = c & 1;
                if (c + 1 < NC) { load_chunk(c + 1, st ^ 1, mb0, nb0); CP_COMMIT(); CP_WAIT(1); }
                else            { CP_WAIT(0); }
                __syncthreads();

                const uint32_t* s0 = (const uint32_t*)smem + st * STAGE_W;
#pragma unroll
                for (int ks = 0; ks < 2; ++ks) {
                    uint32_t ahf[2][4], alf[2][4];
#pragma unroll
                    for (int mt = 0; mt < 2; ++mt) {
                        const int rb = wm * 32 + mt * 16;
                        const uint32_t* pa = s0 + (rb + g) * STR + ks * 8 + tg;
                        ahf[mt][0] = pa[0];           ahf[mt][2] = pa[4];
                        ahf[mt][1] = pa[8 * STR];     ahf[mt][3] = pa[8 * STR + 4];
                        const uint32_t* pl = pa + TILE_W;
                        alf[mt][0] = pl[0];           alf[mt][2] = pl[4];
                        alf[mt][1] = pl[8 * STR];     alf[mt][3] = pl[8 * STR + 4];
                    }
#pragma unroll
                    for (int nt = 0; nt < 8; ++nt) {
                        const int nb = wn * 64 + nt * 8;
                        const uint32_t* pb = s0 + 2 * TILE_W + (nb + g) * STR + ks * 8 + tg;
                        const uint32_t bh0 = pb[0], bh1 = pb[4];
                        const uint32_t* pbl = pb + TILE_W;
                        const uint32_t bl0 = pbl[0], bl1 = pbl[4];
#pragma unroll
                        for (int mt = 0; mt < 2; ++mt) {
                            mma16816(acc[mt][nt], ahf[mt], bh0, bh1);
                            mma16816(acc[mt][nt], ahf[mt], bl0, bl1);
                            mma16816(acc[mt][nt], alf[mt], bh0, bh1);
                        }
                    }
                }
                __syncthreads();
            }

#pragma unroll
            for (int mt = 0; mt < 2; ++mt) {
#pragma unroll
                for (int nt = 0; nt < 8; ++nt) {
                    const int m1 = mb0 + wm * 32 + mt * 16 + g;
                    const int m2 = m1 + 8;
                    const int n  = nb0 + wn * 64 + nt * 8 + tg * 2;
                    const float* a = acc[mt][nt];
                    if (MODE == 4) {
                        const float i1 = 1.0f / rs[zb * SEQ + m1];
                        const float i2 = 1.0f / rs[zb * SEQ + m2];
                        float2 v0; v0.x = a[0] * i1; v0.y = a[1] * i1;
                        float2 v1; v1.x = a[2] * i2; v1.y = a[3] * i2;
                        *(float2*)(Cf + zb * sC + (size_t)m1 * DM + n) = v0;
                        *(float2*)(Cf + zb * sC + (size_t)m2 * DM + n) = v1;
                    } else if (MODE == 0) {
#pragma unroll
                        for (int e = 0; e < 4; ++e) {
                            const int m = (e < 2) ? m1 : m2;
                            const int nn = n + (e & 1);
                            store_blk2(Cb + (size_t)(m >> 11) * 8388608u,
                                       m & 2047, nn, 32, a[e] + bias[nn]);
                        }
                    } else if (MODE == 3) {
                        float e0 = __expf(a[0] * alpha), e1 = __expf(a[1] * alpha);
                        float e2 = __expf(a[2] * alpha), e3 = __expf(a[3] * alpha);
                        atomicAdd(&rs[zb * SEQ + m1], e0 + e1);
                        atomicAdd(&rs[zb * SEQ + m2], e2 + e3);
                        uint8_t* base = Cb + zb * 16777216u;
                        store_blk2(base, m1, n,     64, e0);
                        store_blk2(base, m1, n + 1, 64, e1);
                        store_blk2(base, m2, n,     64, e2);
                        store_blk2(base, m2, n + 1, 64, e3);
                    } else {  // MODE 2: Vt rows=v=m, k=s=n
                        uint8_t* base = Cb + zb * 8388608u;
#pragma unroll
                        for (int e = 0; e < 4; ++e) {
                            const int m = (e < 2) ? m1 : m2;
                            const int nn = n + (e & 1);
                            store_blk2(base, m, nn, 64, a[e] + bias[m]);
                        }
                    }
                }
            }
            __syncthreads();
        }
    }
#endif
}

// ---------------------------------------------------------------------------
// f32 -> blocked split-bf16 (K fixed = 1024). z selects among 3 tensors.
// ---------------------------------------------------------------------------
__global__ void __launch_bounds__(256) split3_k(
    const float* __restrict__ x0, const float* __restrict__ x1,
    const float* __restrict__ x2,
    uint8_t* __restrict__ d0, uint8_t* __restrict__ d1,
    uint8_t* __restrict__ d2, int nunits)
{
    const int z = blockIdx.z;
    const float* x = (z == 0) ? x0 : (z == 1) ? x1 : x2;
    uint8_t*   dst = (z == 0) ? d0 : (z == 1) ? d1 : d2;
    for (int u = blockIdx.x * 256 + threadIdx.x; u < nunits; u += gridDim.x * 256) {
        const int r  = u >> 7;        // row (K=1024 -> 128 16B-units/row)
        const int ku = u & 127;
        const int kc = ku >> 2;
        const int q  = ku & 3;
        const float4 f0 = *(const float4*)(x + ((size_t)r << 10) + (ku << 3));
        const float4 f1 = *(const float4*)(x + ((size_t)r << 10) + (ku << 3) + 4);
        const float v[8] = {f0.x, f0.y, f0.z, f0.w, f1.x, f1.y, f1.z, f1.w};
        __nv_bfloat16 h[8], l[8];
#pragma unroll
        for (int i = 0; i < 8; ++i) split2(v[i], h[i], l[i]);
        uint4 hv, lv;
        hv.x = pkbf2(h[0], h[1]); hv.y = pkbf2(h[2], h[3]);
        hv.z = pkbf2(h[4], h[5]); hv.w = pkbf2(h[6], h[7]);
        lv.x = pkbf2(l[0], l[1]); lv.y = pkbf2(l[2], l[3]);
        lv.z = pkbf2(l[4], l[5]); lv.w = pkbf2(l[6], l[7]);
        const size_t blk = ((((size_t)(r >> 8)) << 5) + kc) << 15;  // nkc = 32
        const uint32_t ro = (uint32_t)(r & 255) * 128 + q * 16;
        *(uint4*)(dst + blk + SWZ128(ro))      = hv;
        *(uint4*)(dst + blk + SWZ128(ro + 64)) = lv;
    }
}

__global__ void __launch_bounds__(1024) zero_k(float* __restrict__ p, int n)
{
    int i = blockIdx.x * 1024 + threadIdx.x;
    if (i < n) p[i] = 0.0f;
}

// ---------------------------------------------------------------------------
extern "C" void kernel_launch(void* const* d_in, const int* in_sizes, int n_in,
                              void* d_out, int out_size)
{
    (void)in_sizes; (void)n_in; (void)out_size;
    const float* q  = (const float*)d_in[0];
    const float* kx = (const float*)d_in[1];
    const float* vx = (const float*)d_in[2];
    const float* Wq = (const float*)d_in[3];
    const float* bq = (const float*)d_in[4];
    const float* Wk = (const float*)d_in[5];
    const float* bk = (const float*)d_in[6];
    const float* Wv = (const float*)d_in[7];
    const float* bv = (const float*)d_in[8];
    float* out = (float*)d_out;

    uint8_t *Xq, *Xk, *Xv, *Wqb, *Wkb, *Wvb, *Qb, *Kb, *Vt, *Pb;
    float* rs;
    cudaGetSymbolAddress((void**)&Xq,  g_Xq);  cudaGetSymbolAddress((void**)&Xk,  g_Xk);
    cudaGetSymbolAddress((void**)&Xv,  g_Xv);
    cudaGetSymbolAddress((void**)&Wqb, g_Wq);  cudaGetSymbolAddress((void**)&Wkb, g_Wk);
    cudaGetSymbolAddress((void**)&Wvb, g_Wv);
    cudaGetSymbolAddress((void**)&Qb,  g_Qb);  cudaGetSymbolAddress((void**)&Kb,  g_Kb);
    cudaGetSymbolAddress((void**)&Vt,  g_Vt);  cudaGetSymbolAddress((void**)&Pb,  g_Pb);
    cudaGetSymbolAddress((void**)&rs,  g_rs);

    cudaFuncSetAttribute(tc_gemm<0>, cudaFuncAttributeMaxDynamicSharedMemorySize, SMEM_TOTAL);
    cudaFuncSetAttribute(tc_gemm<2>, cudaFuncAttributeMaxDynamicSharedMemorySize, SMEM_TOTAL);
    cudaFuncSetAttribute(tc_gemm<3>, cudaFuncAttributeMaxDynamicSharedMemorySize, SMEM_TOTAL);
    cudaFuncSetAttribute(tc_gemm<4>, cudaFuncAttributeMaxDynamicSharedMemorySize, SMEM_TOTAL);

    // 1. splits (inputs z=3, weights z=3) + zero row sums
    split3_k<<<dim3(2048, 1, 3), 256>>>(q, kx, vx, Xq, Xk, Xv, NTOK * DIN / 8);
    split3_k<<<dim3(512,  1, 3), 256>>>(Wq, Wk, Wv, Wqb, Wkb, Wvb, DM * DIN / 8);
    zero_k<<<(BN * SEQ + 1023) / 1024, 1024>>>(rs, BN * SEQ);

    // 2. Q and K projections in ONE launch (z selects operand set)
    tc_gemm<0><<<dim3(DM / 256, NTOK / 256, 2), 256, SMEM_TOTAL>>>(
        Xq, Wqb, Xk, Wkb, bq, bk, nullptr, Qb, Kb, nullptr,
        DIN, 1.0f, 0, 0, 0);

    // 3. Vt = Wv * Xv^T (+bv), vectorized blocked epilogue (no scatter)
    tc_gemm<2><<<dim3(SEQ / 256, DM / 256, BN), 256, SMEM_TOTAL>>>(
        Wvb, Xv, nullptr, nullptr, bv, nullptr, nullptr, Vt, nullptr, nullptr,
        DIN, 1.0f, 0, 8388608u, 0);

    // 4. scores + exp + row sums -> blocked P
    tc_gemm<3><<<dim3(SEQ / 256, SEQ / 256, BN), 256, SMEM_TOTAL>>>(
        Qb, Kb, nullptr, nullptr, nullptr, nullptr, nullptr, Pb, nullptr, rs,
        DM, 0.03125f, 8388608u, 8388608u, 0);

    // 5. O = (P * Vt^T) / rowsum
    tc_gemm<4><<<dim3(DM / 256, SEQ / 256, BN), 256, SMEM_TOTAL>>>(
        Pb, Vt, nullptr, nullptr, nullptr, nullptr, out, nullptr, nullptr, rs,
        SEQ, 1.0f, 16777216u, 8388608u, (size_t)SEQ * DM);
}

// round 9
// speedup vs baseline: 3.4470x; 1.9241x over previous
#include <cuda_runtime.h>
#include <cuda_bf16.h>
#include <cuda_fp16.h>
#include <cstdint>

// ---------------------------------------------------------------------------
// Problem constants
// ---------------------------------------------------------------------------
#define BN   8
#define SEQ  2048
#define DIN  1024
#define DM   1024
#define NTOK (BN*SEQ)          // 16384

// ---------------------------------------------------------------------------
// Blocked fp16 operand layout (v2):
//   operand[row, k] stored as 32KB blocks indexed [row/256][k/64].
//   Block: 256 rows x 128B; row = 64 fp16 k-values, SW128-swizzled.
//   GEMM chunk (K=64) load = TWO contiguous 32KB cp.async.bulk copies.
// ---------------------------------------------------------------------------
#define SWZ128(off) ((off) ^ (((off) >> 3) & 0x70))

__device__ uint8_t g_Xq[(size_t)NTOK*DIN*2];
__device__ uint8_t g_Xk[(size_t)NTOK*DIN*2];
__device__ uint8_t g_Xv[(size_t)NTOK*DIN*2];
__device__ uint8_t g_Wq[(size_t)DM*DIN*2];
__device__ uint8_t g_Wk[(size_t)DM*DIN*2];
__device__ uint8_t g_Wv[(size_t)DM*DIN*2];
__device__ uint8_t g_Qb[(size_t)NTOK*DM*2];          // 4MB/batch, nkc=16
__device__ uint8_t g_Kb[(size_t)NTOK*DM*2];
__device__ uint8_t g_Vt[(size_t)BN*DM*SEQ*2];        // rows=v, k=s, nkc=32, 4MB/batch
__device__ uint8_t g_Pb[(size_t)BN*SEQ*SEQ*2];       // rows=q, k=s, nkc=32, 8MB/batch
__device__ float   g_rs[(size_t)BN*SEQ];

// ---------------------------------------------------------------------------
// Helpers available on base compute_103
// ---------------------------------------------------------------------------
__device__ __forceinline__ uint32_t smem_u32(const void* p) {
    uint32_t a;
    asm("{ .reg .u64 t; cvta.to.shared.u64 t, %1; cvt.u32.u64 %0, t; }"
        : "=r"(a) : "l"(p));
    return a;
}
__device__ __forceinline__ void cp16(uint32_t dst, const void* src) {
    asm volatile("cp.async.cg.shared.global [%0], [%1], 16;" :: "r"(dst), "l"(src));
}
#define CP_COMMIT()  asm volatile("cp.async.commit_group;" ::: "memory")
#define CP_WAIT(N)   asm volatile("cp.async.wait_group %0;" :: "n"(N) : "memory")

__device__ __forceinline__ void mma16816h(float* c, const uint32_t* a,
                                          uint32_t b0, uint32_t b1) {
    asm volatile(
        "mma.sync.aligned.m16n8k16.row.col.f32.f16.f16.f32 "
        "{%0,%1,%2,%3}, {%4,%5,%6,%7}, {%8,%9}, {%0,%1,%2,%3};"
        : "+f"(c[0]), "+f"(c[1]), "+f"(c[2]), "+f"(c[3])
        : "r"(a[0]), "r"(a[1]), "r"(a[2]), "r"(a[3]), "r"(b0), "r"(b1));
}

__device__ __forceinline__ uint32_t pkh2(__half a, __half b) {
    __half2 t; t.x = a; t.y = b;
    return *(uint32_t*)&t;
}
// scalar fp16 store into blocked layout (fallback path)
__device__ __forceinline__ void store_blk1(uint8_t* base, int row, int k,
                                           int nkc, float v) {
    const size_t blk = (((size_t)(row >> 8)) * nkc + (k >> 6)) << 15;
    const uint32_t off = (uint32_t)(row & 255) * 128 + (k & 63) * 2;
    *(__half*)(base + blk + SWZ128(off)) = __float2half(v);
}

// bulk copy (UBLKCP): contiguous gmem -> smem, completion via mbarrier tx-bytes
__device__ __forceinline__ void bulk_ld(uint32_t dst, const void* src,
                                        uint32_t bytes, uint32_t mbar) {
    asm volatile(
        "cp.async.bulk.shared::cluster.global.mbarrier::complete_tx::bytes "
        "[%0], [%1], %2, [%3];"
        :: "r"(dst), "l"(src), "r"(bytes), "r"(mbar) : "memory");
}
#define MBAR_INIT(addr, cnt) \
    asm volatile("mbarrier.init.shared.b64 [%0], %1;" :: "r"((uint32_t)(addr)), "r"((uint32_t)(cnt)) : "memory")
#define MBAR_EXPECT(addr, tx) \
    asm volatile("mbarrier.arrive.expect_tx.shared.b64 _, [%0], %1;" :: "r"((uint32_t)(addr)), "r"((uint32_t)(tx)) : "memory")
#define MBAR_WAIT(mbar, par) do { \
    uint32_t _m = (uint32_t)(mbar), _p = (uint32_t)(par), _d; \
    asm volatile("{\n\t.reg .pred p;\n\t" \
        "mbarrier.try_wait.parity.acquire.cta.shared::cta.b64 p, [%1], %2;\n\t" \
        "selp.b32 %0, 1, 0, p;\n\t}" : "=r"(_d) : "r"(_m), "r"(_p) : "memory"); \
    if (!_d) { \
        asm volatile("{\n\t.reg .pred P1;\n\t" \
            "WL_%=:\n\t" \
            "mbarrier.try_wait.parity.acquire.cta.shared::cta.b64 P1, [%0], %1, 0x989680;\n\t" \
            "@P1 bra.uni WD_%=;\n\tbra.uni WL_%=;\n\tWD_%=:\n\t}" \
            :: "r"(_m), "r"(_p) : "memory"); \
    } \
} while (0)

// ---------------------------------------------------------------------------
// tcgen05 helpers — ONLY compiled when the build has a compute_103a pass.
// ---------------------------------------------------------------------------
#if defined(__CUDA_ARCH_FEAT_SM103_ALL)
__device__ __forceinline__ uint32_t elect_one_pred() {
    uint32_t pred;
    asm volatile(
        "{\n\t.reg .pred p;\n\t"
        "elect.sync _|p, 0xFFFFFFFF;\n\t"
        "selp.b32 %0, 1, 0, p;\n\t}"
        : "=r"(pred));
    return pred;
}
#define TCGEN05_ALLOC(a, n) \
    asm volatile("tcgen05.alloc.cta_group::1.sync.aligned.shared::cta.b32 [%0], %1;" \
        :: "r"((uint32_t)(a)), "r"((uint32_t)(n)) : "memory")
#define TCGEN05_RELINQUISH() \
    asm volatile("tcgen05.relinquish_alloc_permit.cta_group::1.sync.aligned;")
#define TCGEN05_DEALLOC(t, n) \
    asm volatile("tcgen05.dealloc.cta_group::1.sync.aligned.b32 %0, %1;" :: "r"(t), "r"((uint32_t)(n)))
#define TCGEN05_COMMIT(m) \
    asm volatile("tcgen05.commit.cta_group::1.mbarrier::arrive::one.shared::cluster.b64 [%0];" \
        :: "r"((uint32_t)(m)) : "memory")
#define TCGEN05_WAIT_LD()    asm volatile("tcgen05.wait::ld.sync.aligned;" ::: "memory")
#define TCGEN05_FENCE_AFTER() asm volatile("tcgen05.fence::after_thread_sync;" ::: "memory")
#define TCGEN05_LD_32X32B_X32(r, ta) \
    asm volatile( \
        "tcgen05.ld.sync.aligned.32x32b.x32.b32 " \
        "{%0, %1, %2, %3, %4, %5, %6, %7, " \
        " %8, %9, %10, %11, %12, %13, %14, %15, " \
        " %16, %17, %18, %19, %20, %21, %22, %23, " \
        " %24, %25, %26, %27, %28, %29, %30, %31}, [%32];" \
        : "=r"((r)[0]),  "=r"((r)[1]),  "=r"((r)[2]),  "=r"((r)[3]), \
          "=r"((r)[4]),  "=r"((r)[5]),  "=r"((r)[6]),  "=r"((r)[7]), \
          "=r"((r)[8]),  "=r"((r)[9]),  "=r"((r)[10]), "=r"((r)[11]), \
          "=r"((r)[12]), "=r"((r)[13]), "=r"((r)[14]), "=r"((r)[15]), \
          "=r"((r)[16]), "=r"((r)[17]), "=r"((r)[18]), "=r"((r)[19]), \
          "=r"((r)[20]), "=r"((r)[21]), "=r"((r)[22]), "=r"((r)[23]), \
          "=r"((r)[24]), "=r"((r)[25]), "=r"((r)[26]), "=r"((r)[27]), \
          "=r"((r)[28]), "=r"((r)[29]), "=r"((r)[30]), "=r"((r)[31]) \
        : "r"(ta))
static constexpr uint64_t SMEM_DESC_BASE_SW128 =
    (uint64_t(2)  << 61) | (uint64_t(1) << 46) | (uint64_t(64) << 32) | (uint64_t(1) << 16);
#define MAKE_SMEM_DESC(ba) (SMEM_DESC_BASE_SW128 | ((uint64_t)((ba) >> 4) & 0x3FFF))
__device__ __forceinline__ void mma_f16_ss(uint32_t d, uint64_t ad, uint64_t bd,
                                           uint32_t idesc, bool acc) {
    uint32_t en = acc ? 1u : 0u;
    asm volatile(
        "{\n\t.reg .pred p;\n\t"
        "setp.ne.u32 p, %5, 0;\n\t"
        "tcgen05.mma.cta_group::1.kind::f16 [%0], %1, %2, %3, {%4, %4, %4, %4}, p;\n\t"
        "}"
        :: "r"(d), "l"(ad), "l"(bd), "r"(idesc), "r"(0u), "r"(en)
        : "memory");
}
#endif  // __CUDA_ARCH_FEAT_SM103_ALL

// ---------------------------------------------------------------------------
// GEMM: C[M,N] = A[M,K] * B[N,K]^T, single-pass fp16 operands (blocked).
// tcgen05: CTA 256x256, TK=64, two M=128 TMEM accumulators, 3-stage pipeline,
// 2x32KB bulk loads/chunk, single-elected-thread mainloop, deferred MMA wait.
// MODE 0: dual projection (z selects {Xq,Wq,bq,Qb}/{Xk,Wk,bk,Kb}), bias[n], nkc=16
// MODE 2: Vt = Wv * Xv^T (+bias[m]); out rows=v, k=s, nkc=32
// MODE 3: e=expf(acc*alpha) f16 out + row-sum atomics [scores->P], nkc=32
// MODE 4: f32 out = acc / rowsum[m]  [PV]
// ---------------------------------------------------------------------------
constexpr int OFF_B  = 32768;
constexpr int STAGE  = 65536;                     // 32KB A + 32KB B
constexpr int SMEM_DATA = 1024;
constexpr int SMEM_TOTAL = SMEM_DATA + 3 * STAGE; // 197632

template <int MODE>
__global__ void __launch_bounds__(256, 1) tc_gemm(
    const uint8_t* __restrict__ Ab, const uint8_t* __restrict__ Bb,
    const uint8_t* __restrict__ A2b, const uint8_t* __restrict__ B2b,
    const float* __restrict__ bias, const float* __restrict__ bias2,
    float* __restrict__ Cf, uint8_t* __restrict__ Cb, uint8_t* __restrict__ C2b,
    float* __restrict__ rs,
    int K, float alpha,
    size_t sAb, size_t sBb, size_t sC)
{
    extern __shared__ char smem[];
    const int tid   = threadIdx.x;
    const size_t zb = blockIdx.z;
    const int m0    = blockIdx.y * 256;
    const int n0    = blockIdx.x * 256;
    const int NC    = K >> 6;                 // 64-k chunks

    if (MODE == 0 && zb == 1) {
        Ab = A2b; Bb = B2b; Cb = C2b; bias = bias2;
    }
    Ab += zb * sAb;  Bb += zb * sBb;
    const size_t blkA0 = ((size_t)(m0 >> 8)) * NC;
    const size_t blkB0 = ((size_t)(n0 >> 8)) * NC;

#if defined(__CUDA_ARCH_FEAT_SM103_ALL)
    // ======================= tcgen05 path (sm_103a) ========================
    const uint32_t sb = smem_u32(smem);

    if (tid < 32) TCGEN05_ALLOC(sb + 0, 512);
    if (tid >= 32 && tid < 64) TCGEN05_RELINQUISH();
    if (tid == 0) {
#pragma unroll
        for (int s = 0; s < 3; ++s) {
            MBAR_INIT(sb + 8  + 8 * s, 1);   // full (tx-based)
            MBAR_INIT(sb + 32 + 8 * s, 1);   // mma done
        }
    }
    __syncthreads();
    uint32_t tmem;
    asm volatile("ld.shared.b32 %0, [%1];" : "=r"(tmem) : "r"(sb + 0));

    // kind::f16, atype=btype=F16 (0), dtype F32, N=256, M=128 per dispatch
    constexpr uint32_t IDESC =
        (1u << 4) | ((256 / 8) << 17) | ((128 / 16) << 24);

    if (tid < 32 && elect_one_pred()) {
        auto load_chunk = [&](int kc, int st) {
            const uint32_t full = sb + 8 + 8 * st;
            const uint32_t base = sb + SMEM_DATA + st * STAGE;
            MBAR_EXPECT(full, STAGE);
            bulk_ld(base,         Ab + ((blkA0 + kc) << 15), 32768, full);
            bulk_ld(base + OFF_B, Bb + ((blkB0 + kc) << 15), 32768, full);
        };

        load_chunk(0, 0);
        if (NC > 1) load_chunk(1, 1);
        if (NC > 2) load_chunk(2, 2);

        int fph[3] = {0, 0, 0}, mph[3] = {0, 0, 0};
        for (int c = 0; c < NC; ++c) {
            const int st = c % 3;
            MBAR_WAIT(sb + 8 + 8 * st, fph[st]);
            fph[st] ^= 1;

            const uint32_t base = sb + SMEM_DATA + st * STAGE;
            const uint64_t daA0 = MAKE_SMEM_DESC(base);
            const uint64_t daA1 = MAKE_SMEM_DESC(base + 16384);
            const uint64_t db   = MAKE_SMEM_DESC(base + OFF_B);
#pragma unroll
            for (int half = 0; half < 2; ++half) {
                const uint64_t da = half ? daA1 : daA0;
                const uint32_t dt = tmem + half * 256;
#pragma unroll
                for (int ks = 0; ks < 4; ++ks)   // 16 fp16 per step = +2 units
                    mma_f16_ss(dt, da + ks * 2, db + ks * 2, IDESC,
                               !(c == 0 && ks == 0));
            }
            TCGEN05_COMMIT(sb + 32 + 8 * st);

            if (c > 0) {
                const int sp = (c - 1) % 3;
                MBAR_WAIT(sb + 32 + 8 * sp, mph[sp]);
                mph[sp] ^= 1;
                if (c + 2 < NC) load_chunk(c + 2, sp);
            }
        }
        MBAR_WAIT(sb + 32 + 8 * ((NC - 1) % 3), mph[(NC - 1) % 3]);
    }
    __syncthreads();
    TCGEN05_FENCE_AFTER();

    // epilogue: warps 0-3 -> D0 (rows 0-127), warps 4-7 -> D1 (rows 128-255)
    {
        const int half = tid >> 7;
        const int w4   = (tid >> 5) & 3;
        const int lid  = tid & 31;
        const int m    = m0 + half * 128 + w4 * 32 + lid;
        const uint32_t dt = tmem + half * 256;
        float inv = 1.0f, lsum = 0.0f, bm = 0.0f;
        if (MODE == 4) inv = 1.0f / rs[zb * SEQ + m];
        if (MODE == 2) bm  = bias[m];
        for (int j0 = 0; j0 < 256; j0 += 32) {
            uint32_t r[32];
            TCGEN05_LD_32X32B_X32(r, dt + j0);
            TCGEN05_WAIT_LD();
            if (MODE == 4) {
                float4* dst = (float4*)(Cf + zb * sC + (size_t)m * DM + n0 + j0);
#pragma unroll
                for (int i = 0; i < 8; ++i) {
                    float4 v;
                    v.x = __uint_as_float(r[4 * i + 0]) * inv;
                    v.y = __uint_as_float(r[4 * i + 1]) * inv;
                    v.z = __uint_as_float(r[4 * i + 2]) * inv;
                    v.w = __uint_as_float(r[4 * i + 3]) * inv;
                    dst[i] = v;
                }
            } else {   // MODE 0 / 2 / 3: blocked fp16 store (32 vals = 64B)
                uint32_t H[16];
#pragma unroll
                for (int i = 0; i < 32; i += 2) {
                    float v0, v1;
                    if (MODE == 3) {
                        v0 = __expf(__uint_as_float(r[i])     * alpha);
                        v1 = __expf(__uint_as_float(r[i + 1]) * alpha);
                        lsum += v0 + v1;
                    } else if (MODE == 0) {
                        v0 = __uint_as_float(r[i])     + bias[n0 + j0 + i];
                        v1 = __uint_as_float(r[i + 1]) + bias[n0 + j0 + i + 1];
                    } else {
                        v0 = __uint_as_float(r[i])     + bm;
                        v1 = __uint_as_float(r[i + 1]) + bm;
                    }
                    H[i >> 1] = pkh2(__float2half(v0), __float2half(v1));
                }
                uint8_t* base;
                size_t blk;
                const int row = m & 255;
                if (MODE == 0) {          // Q/K: 4MB/batch(by m), nkc = 16
                    base = Cb + (size_t)(m >> 11) * 4194304u;
                    blk  = ((((size_t)((m & 2047) >> 8)) * 16) + ((n0 + j0) >> 6)) << 15;
                } else if (MODE == 3) {   // P: 8MB/batch, nkc = 32
                    base = Cb + zb * 8388608u;
                    blk  = ((((size_t)(m >> 8)) * 32) + ((n0 + j0) >> 6)) << 15;
                } else {                  // Vt: 4MB/batch, nkc = 32
                    base = Cb + zb * 4194304u;
                    blk  = ((((size_t)(m >> 8)) * 32) + ((n0 + j0) >> 6)) << 15;
                }
                const uint32_t u0 = (uint32_t)(((n0 + j0) & 63) >> 3);  // 0 or 4
#pragma unroll
                for (int q = 0; q < 4; ++q) {
                    uint4 hv;
                    hv.x = H[4*q]; hv.y = H[4*q+1]; hv.z = H[4*q+2]; hv.w = H[4*q+3];
                    *(uint4*)(base + blk +
                              SWZ128((uint32_t)row * 128 + (u0 + q) * 16)) = hv;
                }
            }
        }
        if (MODE == 3) atomicAdd(&rs[zb * SEQ + m], lsum);
    }
    __syncthreads();
    if (tid < 32) TCGEN05_DEALLOC(tmem, 512);

#elif defined(__CUDA_ARCH__)
    // ================= mma.sync fallback (base compute_103) =================
    // Correctness insurance only (sm_103a cubin is the one that runs).
    constexpr int STR = 20;                 // words per 32-fp16 sub-row (padded)
    constexpr int TILE_W = 128 * STR;
    constexpr int STAGE_W = 2 * TILE_W;     // A tile + B tile
    const uint32_t sbase = smem_u32(smem);
    const int lane = tid & 31, wid = tid >> 5;
    const int wm = wid >> 1, wn = wid & 1;
    const int g = lane >> 2, tg = lane & 3;
    const int NC32 = K >> 5;

    auto load_chunk = [&](int c32, int st, int mbase, int nbase) {
        const int q = tid & 3, r0 = tid >> 2;
        const uint32_t dst0 = sbase + st * STAGE_W * 4;
        const int kc = c32 >> 1, h = c32 & 1;
#pragma unroll
        for (int i = 0; i < 2; ++i) {
            const int ra = mbase + r0 + 64 * i;
            const int rb = nbase + r0 + 64 * i;
            const uint32_t ro = (uint32_t)((r0 + 64 * i) * STR + q * 4) * 4;
            const size_t ba = (((size_t)(ra >> 8)) * NC + kc) << 15;
            const size_t bb = (((size_t)(rb >> 8)) * NC + kc) << 15;
            const uint32_t oa = (uint32_t)(ra & 255) * 128 + h * 64 + q * 16;
            const uint32_t ob = (uint32_t)(rb & 255) * 128 + h * 64 + q * 16;
            cp16(dst0 + ro,                Ab + ba + SWZ128(oa));
            cp16(dst0 + TILE_W * 4 + ro,   Bb + bb + SWZ128(ob));
        }
    };

    for (int mh = 0; mh < 2; ++mh) {
        const int mb0 = m0 + mh * 128;
        for (int np = 0; np < 2; ++np) {
            const int nb0 = n0 + np * 128;

            float acc[2][8][4];
#pragma unroll
            for (int a = 0; a < 2; ++a)
#pragma unroll
                for (int b = 0; b < 8; ++b)
#pragma unroll
                    for (int c = 0; c < 4; ++c) acc[a][b][c] = 0.0f;

            load_chunk(0, 0, mb0, nb0); CP_COMMIT();

            for (int c = 0; c < NC32; ++c) {
                const int st = c & 1;
                if (c + 1 < NC32) { load_chunk(c + 1, st ^ 1, mb0, nb0); CP_COMMIT(); CP_WAIT(1); }
                else              { CP_WAIT(0); }
                __syncthreads();

                const uint32_t* s0 = (const uint32_t*)smem + st * STAGE_W;
#pragma unroll
                for (int ks = 0; ks < 2; ++ks) {
                    uint32_t af[2][4];
#pragma unroll
                    for (int mt = 0; mt < 2; ++mt) {
                        const int rb = wm * 32 + mt * 16;
                        const uint32_t* pa = s0 + (rb + g) * STR + ks * 8 + tg;
                        af[mt][0] = pa[0];           af[mt][2] = pa[4];
                        af[mt][1] = pa[8 * STR];     af[mt][3] = pa[8 * STR + 4];
                    }
#pragma unroll
                    for (int nt = 0; nt < 8; ++nt) {
                        const int nb = wn * 64 + nt * 8;
                        const uint32_t* pb = s0 + TILE_W + (nb + g) * STR + ks * 8 + tg;
                        const uint32_t b0 = pb[0], b1 = pb[4];
#pragma unroll
                        for (int mt = 0; mt < 2; ++mt)
                            mma16816h(acc[mt][nt], af[mt], b0, b1);
                    }
                }
                __syncthreads();
            }

#pragma unroll
            for (int mt = 0; mt < 2; ++mt) {
#pragma unroll
                for (int nt = 0; nt < 8; ++nt) {
                    const int m1 = mb0 + wm * 32 + mt * 16 + g;
                    const int m2 = m1 + 8;
                    const int n  = nb0 + wn * 64 + nt * 8 + tg * 2;
                    const float* a = acc[mt][nt];
                    if (MODE == 4) {
                        const float i1 = 1.0f / rs[zb * SEQ + m1];
                        const float i2 = 1.0f / rs[zb * SEQ + m2];
                        float2 v0; v0.x = a[0] * i1; v0.y = a[1] * i1;
                        float2 v1; v1.x = a[2] * i2; v1.y = a[3] * i2;
                        *(float2*)(Cf + zb * sC + (size_t)m1 * DM + n) = v0;
                        *(float2*)(Cf + zb * sC + (size_t)m2 * DM + n) = v1;
                    } else if (MODE == 0) {
#pragma unroll
                        for (int e = 0; e < 4; ++e) {
                            const int m = (e < 2) ? m1 : m2;
                            const int nn = n + (e & 1);
                            store_blk1(Cb + (size_t)(m >> 11) * 4194304u,
                                       m & 2047, nn, 16, a[e] + bias[nn]);
                        }
                    } else if (MODE == 3) {
                        float e0 = __expf(a[0] * alpha), e1 = __expf(a[1] * alpha);
                        float e2 = __expf(a[2] * alpha), e3 = __expf(a[3] * alpha);
                        atomicAdd(&rs[zb * SEQ + m1], e0 + e1);
                        atomicAdd(&rs[zb * SEQ + m2], e2 + e3);
                        uint8_t* base = Cb + zb * 8388608u;
                        store_blk1(base, m1, n,     32, e0);
                        store_blk1(base, m1, n + 1, 32, e1);
                        store_blk1(base, m2, n,     32, e2);
                        store_blk1(base, m2, n + 1, 32, e3);
                    } else {  // MODE 2
                        uint8_t* base = Cb + zb * 4194304u;
#pragma unroll
                        for (int e = 0; e < 4; ++e) {
                            const int m = (e < 2) ? m1 : m2;
                            const int nn = n + (e & 1);
                            store_blk1(base, m, nn, 32, a[e] + bias[m]);
                        }
                    }
                }
            }
            __syncthreads();
        }
    }
#endif
}

// ---------------------------------------------------------------------------
// f32 -> blocked fp16 (K fixed = 1024; nkc = 16). z selects among 3 tensors.
// Each thread-iteration: 8 f32 -> one 16B fp16 unit.
// ---------------------------------------------------------------------------
__global__ void __launch_bounds__(256) split3_k(
    const float* __restrict__ x0, const float* __restrict__ x1,
    const float* __restrict__ x2,
    uint8_t* __restrict__ d0, uint8_t* __restrict__ d1,
    uint8_t* __restrict__ d2, int nunits)
{
    const int z = blockIdx.z;
    const float* x = (z == 0) ? x0 : (z == 1) ? x1 : x2;
    uint8_t*   dst = (z == 0) ? d0 : (z == 1) ? d1 : d2;
    for (int u = blockIdx.x * 256 + threadIdx.x; u < nunits; u += gridDim.x * 256) {
        const int r = u >> 7;         // row (1024 vals -> 128 units)
        const int j = u & 127;        // unit within row
        const float4 f0 = *(const float4*)(x + ((size_t)r << 10) + (j << 3));
        const float4 f1 = *(const float4*)(x + ((size_t)r << 10) + (j << 3) + 4);
        uint4 hv;
        hv.x = pkh2(__float2half(f0.x), __float2half(f0.y));
        hv.y = pkh2(__float2half(f0.z), __float2half(f0.w));
        hv.z = pkh2(__float2half(f1.x), __float2half(f1.y));
        hv.w = pkh2(__float2half(f1.z), __float2half(f1.w));
        const size_t blk = ((((size_t)(r >> 8)) << 4) + (j >> 3)) << 15;  // nkc=16
        const uint32_t ro = (uint32_t)(r & 255) * 128 + (j & 7) * 16;
        *(uint4*)(dst + blk + SWZ128(ro)) = hv;
    }
}

__global__ void __launch_bounds__(1024) zero_k(float* __restrict__ p, int n)
{
    int i = blockIdx.x * 1024 + threadIdx.x;
    if (i < n) p[i] = 0.0f;
}

// ---------------------------------------------------------------------------
extern "C" void kernel_launch(void* const* d_in, const int* in_sizes, int n_in,
                              void* d_out, int out_size)
{
    (void)in_sizes; (void)n_in; (void)out_size;
    const float* q  = (const float*)d_in[0];
    const float* kx = (const float*)d_in[1];
    const float* vx = (const float*)d_in[2];
    const float* Wq = (const float*)d_in[3];
    const float* bq = (const float*)d_in[4];
    const float* Wk = (const float*)d_in[5];
    const float* bk = (const float*)d_in[6];
    const float* Wv = (const float*)d_in[7];
    const float* bv = (const float*)d_in[8];
    float* out = (float*)d_out;

    uint8_t *Xq, *Xk, *Xv, *Wqb, *Wkb, *Wvb, *Qb, *Kb, *Vt, *Pb;
    float* rs;
    cudaGetSymbolAddress((void**)&Xq,  g_Xq);  cudaGetSymbolAddress((void**)&Xk,  g_Xk);
    cudaGetSymbolAddress((void**)&Xv,  g_Xv);
    cudaGetSymbolAddress((void**)&Wqb, g_Wq);  cudaGetSymbolAddress((void**)&Wkb, g_Wk);
    cudaGetSymbolAddress((void**)&Wvb, g_Wv);
    cudaGetSymbolAddress((void**)&Qb,  g_Qb);  cudaGetSymbolAddress((void**)&Kb,  g_Kb);
    cudaGetSymbolAddress((void**)&Vt,  g_Vt);  cudaGetSymbolAddress((void**)&Pb,  g_Pb);
    cudaGetSymbolAddress((void**)&rs,  g_rs);

    cudaFuncSetAttribute(tc_gemm<0>, cudaFuncAttributeMaxDynamicSharedMemorySize, SMEM_TOTAL);
    cudaFuncSetAttribute(tc_gemm<2>, cudaFuncAttributeMaxDynamicSharedMemorySize, SMEM_TOTAL);
    cudaFuncSetAttribute(tc_gemm<3>, cudaFuncAttributeMaxDynamicSharedMemorySize, SMEM_TOTAL);
    cudaFuncSetAttribute(tc_gemm<4>, cudaFuncAttributeMaxDynamicSharedMemorySize, SMEM_TOTAL);

    // 1. splits (inputs, weights) + zero row sums
    split3_k<<<dim3(2048, 1, 3), 256>>>(q, kx, vx, Xq, Xk, Xv, NTOK * DIN / 8);
    split3_k<<<dim3(512,  1, 3), 256>>>(Wq, Wk, Wv, Wqb, Wkb, Wvb, DM * DIN / 8);
    zero_k<<<(BN * SEQ + 1023) / 1024, 1024>>>(rs, BN * SEQ);

    // 2. Q and K projections in ONE launch (z selects operand set)
    tc_gemm<0><<<dim3(DM / 256, NTOK / 256, 2), 256, SMEM_TOTAL>>>(
        Xq, Wqb, Xk, Wkb, bq, bk, nullptr, Qb, Kb, nullptr,
        DIN, 1.0f, 0, 0, 0);

    // 3. Vt = Wv * Xv^T (+bv)
    tc_gemm<2><<<dim3(SEQ / 256, DM / 256, BN), 256, SMEM_TOTAL>>>(
        Wvb, Xv, nullptr, nullptr, bv, nullptr, nullptr, Vt, nullptr, nullptr,
        DIN, 1.0f, 0, 4194304u, 0);

    // 4. scores + exp + row sums -> fp16 P
    tc_gemm<3><<<dim3(SEQ / 256, SEQ / 256, BN), 256, SMEM_TOTAL>>>(
        Qb, Kb, nullptr, nullptr, nullptr, nullptr, nullptr, Pb, nullptr, rs,
        DM, 0.03125f, 4194304u, 4194304u, 0);

    // 5. O = (P * Vt^T) / rowsum
    tc_gemm<4><<<dim3(DM / 256, SEQ / 256, BN), 256, SMEM_TOTAL>>>(
        Pb, Vt, nullptr, nullptr, nullptr, nullptr, out, nullptr, nullptr, rs,
        SEQ, 1.0f, 8388608u, 4194304u, (size_t)SEQ * DM);
}